// round 1
// baseline (speedup 1.0000x reference)
#include <cuda_runtime.h>
#include <cstddef>

#define B_  8
#define N_  2048    // N1 == N2
#define KD  256     // K1D == K2D
#define VD  256     // V1D == V2D
#define AD  128

// ---- scratch (allocation-free rule: __device__ globals) ----
__device__ float g_k1p[B_ * N_ * AD];                 // 8 MB
__device__ float g_k2p[B_ * N_ * AD];                 // 8 MB
__device__ float g_score[(size_t)B_ * N_ * N_];       // 128 MB
__device__ float g_rowmax[B_ * N_];
__device__ float g_R[B_];

#define NEG_INF (-3.402823466e38f)

// ============================================================
// proj: C[M, AD] = A[M, KD] @ W[KD, AD] + bias    (M = B*N)
// which==0 -> g_k1p, which==1 -> g_k2p
// ============================================================
__global__ __launch_bounds__(256) void proj_kernel(const float* __restrict__ A,
                                                   const float* __restrict__ W,
                                                   const float* __restrict__ bias,
                                                   int which) {
    __shared__ float As[8][128];
    __shared__ float Bs[8][128];
    float* C = which ? g_k2p : g_k1p;

    const int t  = threadIdx.x;
    const int tx = t & 15, ty = t >> 4;
    const int m0 = blockIdx.x * 128;

    float acc[8][8];
#pragma unroll
    for (int i = 0; i < 8; i++)
#pragma unroll
        for (int j = 0; j < 8; j++) acc[i][j] = 0.f;

    const int am  = t >> 1;
    const int akq = (t & 1) * 4;
    const int bk  = t >> 5;
    const int bn  = (t & 31) * 4;

    for (int k0 = 0; k0 < KD; k0 += 8) {
        float4 av = *(const float4*)(A + (size_t)(m0 + am) * KD + k0 + akq);
        As[akq + 0][am] = av.x; As[akq + 1][am] = av.y;
        As[akq + 2][am] = av.z; As[akq + 3][am] = av.w;
        float4 bv = *(const float4*)(W + (size_t)(k0 + bk) * AD + bn);
        *(float4*)&Bs[bk][bn] = bv;
        __syncthreads();
#pragma unroll
        for (int kk = 0; kk < 8; kk++) {
            float a[8], bq[8];
#pragma unroll
            for (int i = 0; i < 8; i++) a[i]  = As[kk][ty * 8 + i];
#pragma unroll
            for (int j = 0; j < 8; j++) bq[j] = Bs[kk][tx * 8 + j];
#pragma unroll
            for (int i = 0; i < 8; i++)
#pragma unroll
                for (int j = 0; j < 8; j++) acc[i][j] += a[i] * bq[j];
        }
        __syncthreads();
    }
#pragma unroll
    for (int i = 0; i < 8; i++) {
        const int row = m0 + ty * 8 + i;
#pragma unroll
        for (int j = 0; j < 8; j++) {
            const int col = tx * 8 + j;
            C[(size_t)row * AD + col] = acc[i][j] + bias[col];
        }
    }
}

// ============================================================
// score[b, m, n] = sum_k k1p[b,m,k] * k2p[b,n,k]   (K = AD = 128)
// ============================================================
__global__ __launch_bounds__(256) void score_kernel() {
    __shared__ float As[8][128];
    __shared__ float Bs[8][128];
    const int t  = threadIdx.x;
    const int tx = t & 15, ty = t >> 4;
    const int b  = blockIdx.z;
    const int m0 = blockIdx.y * 128;
    const int n0 = blockIdx.x * 128;

    const float* Ap = g_k1p + (size_t)b * N_ * AD;
    const float* Bp = g_k2p + (size_t)b * N_ * AD;
    float*       Cp = g_score + (size_t)b * N_ * N_;

    float acc[8][8];
#pragma unroll
    for (int i = 0; i < 8; i++)
#pragma unroll
        for (int j = 0; j < 8; j++) acc[i][j] = 0.f;

    const int am  = t >> 1;
    const int akq = (t & 1) * 4;

    for (int k0 = 0; k0 < AD; k0 += 8) {
        float4 av = *(const float4*)(Ap + (size_t)(m0 + am) * AD + k0 + akq);
        As[akq + 0][am] = av.x; As[akq + 1][am] = av.y;
        As[akq + 2][am] = av.z; As[akq + 3][am] = av.w;
        float4 bv = *(const float4*)(Bp + (size_t)(n0 + am) * AD + k0 + akq);
        Bs[akq + 0][am] = bv.x; Bs[akq + 1][am] = bv.y;
        Bs[akq + 2][am] = bv.z; Bs[akq + 3][am] = bv.w;
        __syncthreads();
#pragma unroll
        for (int kk = 0; kk < 8; kk++) {
            float a[8], bq[8];
#pragma unroll
            for (int i = 0; i < 8; i++) a[i]  = As[kk][ty * 8 + i];
#pragma unroll
            for (int j = 0; j < 8; j++) bq[j] = Bs[kk][tx * 8 + j];
#pragma unroll
            for (int i = 0; i < 8; i++)
#pragma unroll
                for (int j = 0; j < 8; j++) acc[i][j] += a[i] * bq[j];
        }
        __syncthreads();
    }
#pragma unroll
    for (int i = 0; i < 8; i++) {
        const int row = m0 + ty * 8 + i;
#pragma unroll
        for (int j = 0; j < 8; j++)
            Cp[(size_t)row * N_ + n0 + tx * 8 + j] = acc[i][j];
    }
}

// ============================================================
// per-row max of score (rows are [b*N_ + n1], length N_)
// ============================================================
__global__ __launch_bounds__(256) void rowmax_kernel() {
    const int row  = blockIdx.x * 8 + (threadIdx.x >> 5);
    const int lane = threadIdx.x & 31;
    const float* s = g_score + (size_t)row * N_;
    float mx = NEG_INF;
    for (int j = lane; j < N_; j += 32) mx = fmaxf(mx, s[j]);
#pragma unroll
    for (int o = 16; o; o >>= 1) mx = fmaxf(mx, __shfl_xor_sync(0xffffffffu, mx, o));
    if (lane == 0) g_rowmax[row] = mx;
}

// per-batch global max of rowmax -> g_R[b]
__global__ __launch_bounds__(256) void batchmax_kernel() {
    __shared__ float sm[256];
    const int b = blockIdx.x, t = threadIdx.x;
    float mx = NEG_INF;
    for (int i = t; i < N_; i += 256) mx = fmaxf(mx, g_rowmax[b * N_ + i]);
    sm[t] = mx; __syncthreads();
    for (int s = 128; s; s >>= 1) {
        if (t < s) sm[t] = fmaxf(sm[t], sm[t + s]);
        __syncthreads();
    }
    if (t == 0) g_R[b] = sm[0];
}

// ============================================================
// o2[b, m, n] = sum_k exp(s[m,k]-rm[m]) * v2[b,k,n] / rowsum[m]
//   M = N1 rows, N = VD cols, K = N2. rowsum computed inline.
// ============================================================
__global__ __launch_bounds__(256) void o2_kernel(const float* __restrict__ v2,
                                                 float* __restrict__ out) {
    __shared__ float As[8][128];
    __shared__ float Bs[8][128];
    __shared__ float redr[256];
    const int t  = threadIdx.x;
    const int tx = t & 15, ty = t >> 4;
    const int b  = blockIdx.z;
    const int m0 = blockIdx.y * 128;
    const int n0 = blockIdx.x * 128;

    const float* Sp = g_score + (size_t)b * N_ * N_;
    const float* Vp = v2 + (size_t)b * N_ * VD;

    const int am  = t >> 1;
    const int akq = (t & 1) * 4;
    const int bkk = t >> 5;
    const int bn  = (t & 31) * 4;
    const float rm = g_rowmax[b * N_ + m0 + am];
    float rsum = 0.f;

    float acc[8][8];
#pragma unroll
    for (int i = 0; i < 8; i++)
#pragma unroll
        for (int j = 0; j < 8; j++) acc[i][j] = 0.f;

    for (int k0 = 0; k0 < N_; k0 += 8) {
        float4 av = *(const float4*)(Sp + (size_t)(m0 + am) * N_ + k0 + akq);
        const float e0 = __expf(av.x - rm), e1 = __expf(av.y - rm);
        const float e2 = __expf(av.z - rm), e3 = __expf(av.w - rm);
        rsum += (e0 + e1) + (e2 + e3);
        As[akq + 0][am] = e0; As[akq + 1][am] = e1;
        As[akq + 2][am] = e2; As[akq + 3][am] = e3;
        float4 bv = *(const float4*)(Vp + (size_t)(k0 + bkk) * VD + n0 + bn);
        *(float4*)&Bs[bkk][bn] = bv;
        __syncthreads();
#pragma unroll
        for (int kk = 0; kk < 8; kk++) {
            float a[8], bq[8];
#pragma unroll
            for (int i = 0; i < 8; i++) a[i]  = As[kk][ty * 8 + i];
#pragma unroll
            for (int j = 0; j < 8; j++) bq[j] = Bs[kk][tx * 8 + j];
#pragma unroll
            for (int i = 0; i < 8; i++)
#pragma unroll
                for (int j = 0; j < 8; j++) acc[i][j] += a[i] * bq[j];
        }
        __syncthreads();
    }
    redr[t] = rsum;
    __syncthreads();
#pragma unroll
    for (int i = 0; i < 8; i++) {
        const int r = ty * 8 + i;
        const float inv = 1.f / (redr[2 * r] + redr[2 * r + 1]);
        const size_t base = (size_t)b * N_ * VD + (size_t)(m0 + r) * VD + n0;
#pragma unroll
        for (int j = 0; j < 8; j++)
            out[base + tx * 8 + j] = acc[i][j] * inv;
    }
}

// ============================================================
// o1[b, m, n] = sum_k exp(s[k,m]-R_b) * v1[b,k,n] / colsum[m]
//   M = N2 (score cols), N = VD, K = N1 (score rows). colsum inline.
// ============================================================
__global__ __launch_bounds__(256) void o1_kernel(const float* __restrict__ v1,
                                                 float* __restrict__ out) {
    __shared__ float As[8][128];
    __shared__ float Bs[8][128];
    __shared__ float redc[8][128];
    const int t  = threadIdx.x;
    const int tx = t & 15, ty = t >> 4;
    const int b  = blockIdx.z;
    const int m0 = blockIdx.y * 128;   // n2 tile
    const int n0 = blockIdx.x * 128;   // v1 col tile

    const float* Sp = g_score + (size_t)b * N_ * N_;
    const float* Vp = v1 + (size_t)b * N_ * VD;
    const float  R  = g_R[b];

    const int akk = t >> 5;
    const int amq = (t & 31) * 4;
    float csum[4] = {0.f, 0.f, 0.f, 0.f};

    float acc[8][8];
#pragma unroll
    for (int i = 0; i < 8; i++)
#pragma unroll
        for (int j = 0; j < 8; j++) acc[i][j] = 0.f;

    for (int k0 = 0; k0 < N_; k0 += 8) {
        float4 sv = *(const float4*)(Sp + (size_t)(k0 + akk) * N_ + m0 + amq);
        const float e0 = __expf(sv.x - R), e1 = __expf(sv.y - R);
        const float e2 = __expf(sv.z - R), e3 = __expf(sv.w - R);
        csum[0] += e0; csum[1] += e1; csum[2] += e2; csum[3] += e3;
        float4 ev = make_float4(e0, e1, e2, e3);
        *(float4*)&As[akk][amq] = ev;
        float4 bv = *(const float4*)(Vp + (size_t)(k0 + akk) * VD + n0 + amq);
        *(float4*)&Bs[akk][amq] = bv;
        __syncthreads();
#pragma unroll
        for (int kk = 0; kk < 8; kk++) {
            float a[8], bq[8];
#pragma unroll
            for (int i = 0; i < 8; i++) a[i]  = As[kk][ty * 8 + i];
#pragma unroll
            for (int j = 0; j < 8; j++) bq[j] = Bs[kk][tx * 8 + j];
#pragma unroll
            for (int i = 0; i < 8; i++)
#pragma unroll
                for (int j = 0; j < 8; j++) acc[i][j] += a[i] * bq[j];
        }
        __syncthreads();
    }
    *(float4*)&redc[akk][amq] = make_float4(csum[0], csum[1], csum[2], csum[3]);
    __syncthreads();
#pragma unroll
    for (int i = 0; i < 8; i++) {
        const int m = ty * 8 + i;
        float cs = 0.f;
#pragma unroll
        for (int g = 0; g < 8; g++) cs += redc[g][m];
        const float inv = 1.f / cs;
        const size_t base = (size_t)b * N_ * VD + (size_t)(m0 + m) * VD + n0;
#pragma unroll
        for (int j = 0; j < 8; j++)
            out[base + tx * 8 + j] = acc[i][j] * inv;
    }
}

// ============================================================
extern "C" void kernel_launch(void* const* d_in, const int* in_sizes, int n_in,
                              void* d_out, int out_size) {
    (void)in_sizes; (void)n_in; (void)out_size;
    const float* k1 = (const float*)d_in[0];
    const float* k2 = (const float*)d_in[1];
    const float* v1 = (const float*)d_in[2];
    const float* v2 = (const float*)d_in[3];
    const float* W1 = (const float*)d_in[4];
    const float* b1 = (const float*)d_in[5];
    const float* W2 = (const float*)d_in[6];
    const float* b2 = (const float*)d_in[7];
    float* out = (float*)d_out;

    float* o2_out = out;                                   // [B, N1, VD]
    float* o1_out = out + (size_t)B_ * N_ * VD;            // [B, N2, VD]

    // 1. projections
    proj_kernel<<<(B_ * N_) / 128, 256>>>(k1, W1, b1, 0);
    proj_kernel<<<(B_ * N_) / 128, 256>>>(k2, W2, b2, 1);

    // 2. score = k1p @ k2p^T per batch
    score_kernel<<<dim3(N_ / 128, N_ / 128, B_), 256>>>();

    // 3. softmax stats
    rowmax_kernel<<<(B_ * N_) / 8, 256>>>();
    batchmax_kernel<<<B_, 256>>>();

    // 4. outputs (softmax applied on-the-fly, sums computed inline)
    o2_kernel<<<dim3(VD / 128, N_ / 128, B_), 256>>>(v2, o2_out);
    o1_kernel<<<dim3(VD / 128, N_ / 128, B_), 256>>>(v1, o1_out);
}

// round 5
// speedup vs baseline: 2.4677x; 2.4677x over previous
#include <cuda_runtime.h>
#include <cuda_fp16.h>
#include <cstdint>
#include <cstddef>

#define B_  8
#define N_  2048
#define KD  256
#define VD  256
#define AD  128
#define NEG_INF (-3.402823466e38f)

typedef unsigned char u8;
typedef unsigned int  u32;

// ------------------- device scratch (allocation-free rule) -------------------
// k-pack: per (b, mt): [hi 32KB][lo 32KB], each = [kc2][128 rows][128B swizzled] bf16
__device__ __align__(16) u8 g_k1pack[(size_t)B_ * 16 * 2 * 32768];   // 8 MB
__device__ __align__(16) u8 g_k2pack[(size_t)B_ * 16 * 2 * 32768];   // 8 MB
// v-pack: per (b, kc32): 32KB = [256 rows(d)][128B swizzled] fp16
__device__ __align__(16) u8 g_v1pack[(size_t)B_ * 32 * 32768];       // 8 MB
__device__ __align__(16) u8 g_v2pack[(size_t)B_ * 32 * 32768];       // 8 MB
__device__ float g_S [(size_t)B_ * N_ * N_];                          // 128 MB
__device__ float g_St[(size_t)B_ * N_ * N_];                          // 128 MB
__device__ float g_rmpart[(size_t)B_ * N_ * 32];                      // 2 MB
__device__ float g_cmpart[(size_t)B_ * N_ * 32];                      // 2 MB
__device__ float g_rowmax[B_ * N_];
__device__ float g_colmax[B_ * N_];

// ------------------- helpers -------------------
__device__ __forceinline__ u32 smem_u32(const void* p) {
    u32 a;
    asm("{ .reg .u64 t; cvta.to.shared.u64 t, %1; cvt.u32.u64 %0, t; }" : "=r"(a) : "l"(p));
    return a;
}
__device__ __forceinline__ u32 f16x2_pack(float a, float b) {
    u32 r;
    asm("cvt.rn.f16x2.f32 %0, %1, %2;" : "=r"(r) : "f"(b), "f"(a));
    return r;
}
__device__ __forceinline__ void split2(float f0, float f1, u32& hi, u32& lo) {
    u32 h;
    asm("cvt.rn.bf16x2.f32 %0, %1, %2;" : "=r"(h) : "f"(f1), "f"(f0));
    float h0 = __uint_as_float(h << 16);
    float h1 = __uint_as_float(h & 0xFFFF0000u);
    u32 l;
    asm("cvt.rn.bf16x2.f32 %0, %1, %2;" : "=r"(l) : "f"(f1 - h1), "f"(f0 - h0));
    hi = h; lo = l;
}
__device__ __forceinline__ void mma_bf16(float* c, const u32* a, u32 b0, u32 b1) {
    asm volatile(
        "mma.sync.aligned.m16n8k16.row.col.f32.bf16.bf16.f32 "
        "{%0,%1,%2,%3}, {%4,%5,%6,%7}, {%8,%9}, {%0,%1,%2,%3};"
        : "+f"(c[0]), "+f"(c[1]), "+f"(c[2]), "+f"(c[3])
        : "r"(a[0]), "r"(a[1]), "r"(a[2]), "r"(a[3]), "r"(b0), "r"(b1));
}
__device__ __forceinline__ void mma_f16(float* c, const u32* a, u32 b0, u32 b1) {
    asm volatile(
        "mma.sync.aligned.m16n8k16.row.col.f32.f16.f16.f32 "
        "{%0,%1,%2,%3}, {%4,%5,%6,%7}, {%8,%9}, {%0,%1,%2,%3};"
        : "+f"(c[0]), "+f"(c[1]), "+f"(c[2]), "+f"(c[3])
        : "r"(a[0]), "r"(a[1]), "r"(a[2]), "r"(a[3]), "r"(b0), "r"(b1));
}
__device__ __forceinline__ void ldsm4(u32* r, u32 addr) {
    asm volatile("ldmatrix.sync.aligned.m8n8.x4.shared.b16 {%0,%1,%2,%3}, [%4];"
                 : "=r"(r[0]), "=r"(r[1]), "=r"(r[2]), "=r"(r[3]) : "r"(addr));
}
#define CP_ASYNC16(dst, src)                                                \
    asm volatile("cp.async.cg.shared.global [%0], [%1], 16;"                \
                 :: "r"(dst), "l"(__cvta_generic_to_global(src)))
#define CP_COMMIT()  asm volatile("cp.async.commit_group;")
#define CP_WAIT0()   asm volatile("cp.async.wait_group 0;")
#define CP_WAIT1()   asm volatile("cp.async.wait_group 1;")

// ============================================================
// proj: C = A[M,256] @ W[256,128] + bias -> split bf16 hi/lo swizzled pack
// ============================================================
__global__ __launch_bounds__(256) void proj_kernel(const float* __restrict__ A,
                                                   const float* __restrict__ W,
                                                   const float* __restrict__ bias,
                                                   int which) {
    __shared__ float As[8][128];
    __shared__ float Bs[8][128];
    const int t = threadIdx.x, tx = t & 15, ty = t >> 4;
    const int m0 = blockIdx.x * 128;
    float acc[8][8];
#pragma unroll
    for (int i = 0; i < 8; i++)
#pragma unroll
        for (int j = 0; j < 8; j++) acc[i][j] = 0.f;
    const int am = t >> 1, akq = (t & 1) * 4, bk = t >> 5, bn = (t & 31) * 4;
    for (int k0 = 0; k0 < KD; k0 += 8) {
        float4 av = *(const float4*)(A + (size_t)(m0 + am) * KD + k0 + akq);
        As[akq + 0][am] = av.x; As[akq + 1][am] = av.y;
        As[akq + 2][am] = av.z; As[akq + 3][am] = av.w;
        *(float4*)&Bs[bk][bn] = *(const float4*)(W + (size_t)(k0 + bk) * AD + bn);
        __syncthreads();
#pragma unroll
        for (int kk = 0; kk < 8; kk++) {
            float a[8], b[8];
#pragma unroll
            for (int i = 0; i < 8; i++) a[i] = As[kk][ty * 8 + i];
#pragma unroll
            for (int j = 0; j < 8; j++) b[j] = Bs[kk][tx * 8 + j];
#pragma unroll
            for (int i = 0; i < 8; i++)
#pragma unroll
                for (int j = 0; j < 8; j++) acc[i][j] += a[i] * b[j];
        }
        __syncthreads();
    }
    // epilogue -> split bf16 packed swizzled tiles (device-side symbol resolution)
    const int b_ = m0 / N_, mt = (m0 % N_) / 128;
    u8* hibase = (which ? g_k2pack : g_k1pack) + ((size_t)(b_ * 16 + mt) * 2) * 32768;
    u8* lobase = hibase + 32768;
    const int kc = tx >> 3;
    float bb[8];
#pragma unroll
    for (int j = 0; j < 8; j++) bb[j] = bias[tx * 8 + j];
#pragma unroll
    for (int i = 0; i < 8; i++) {
        const int row = ty * 8 + i;
        const u32 xv = (u32)((row & 7) * 16);
#pragma unroll
        for (int jq = 0; jq < 2; jq++) {
            float f0 = acc[i][jq * 4 + 0] + bb[jq * 4 + 0];
            float f1 = acc[i][jq * 4 + 1] + bb[jq * 4 + 1];
            float f2 = acc[i][jq * 4 + 2] + bb[jq * 4 + 2];
            float f3 = acc[i][jq * 4 + 3] + bb[jq * 4 + 3];
            u32 h01, l01, h23, l23;
            split2(f0, f1, h01, l01); split2(f2, f3, h23, l23);
            const int klocal = (tx & 7) * 8 + jq * 4;
            const u32 off = (u32)(kc * 16384 + row * 128) + (((u32)(klocal * 2)) ^ xv);
            *(uint2*)(hibase + off) = make_uint2(h01, h23);
            *(uint2*)(lobase + off) = make_uint2(l01, l23);
        }
    }
}

// ============================================================
// vpack: v[b][k][d] fp32 -> fp16 swizzled tiles per (b,kc): [256 d-rows][64 k-hw]
// which resolves destination INSIDE the kernel (device symbol).
// ============================================================
__global__ __launch_bounds__(256) void vpack_kernel(const float* __restrict__ v,
                                                    int which) {
    __shared__ float sv[64][68];  // [d][k]
    u8* dst = which ? g_v2pack : g_v1pack;
    const int b = blockIdx.y, kc = blockIdx.x;
    const int t = threadIdx.x;
    u8* tile = dst + ((size_t)b * 32 + kc) * 32768;
    for (int dc = 0; dc < 4; dc++) {
#pragma unroll
        for (int i = 0; i < 4; i++) {
            const int q = t + i * 256;
            const int kr = q >> 4, dl = (q & 15) * 4;
            float4 f = *(const float4*)(v + ((size_t)b * N_ + kc * 64 + kr) * VD + dc * 64 + dl);
            sv[dl + 0][kr] = f.x; sv[dl + 1][kr] = f.y;
            sv[dl + 2][kr] = f.z; sv[dl + 3][kr] = f.w;
        }
        __syncthreads();
        const int dl = t >> 2, q = t & 3;
        const int row = dc * 64 + dl;
        const u32 xv = (u32)((row & 7) * 16);
#pragma unroll
        for (int j = 0; j < 4; j++) {
            const int k0 = q * 16 + j * 4;
            u32 p01 = f16x2_pack(sv[dl][k0 + 0], sv[dl][k0 + 1]);
            u32 p23 = f16x2_pack(sv[dl][k0 + 2], sv[dl][k0 + 3]);
            *(uint2*)(tile + row * 128 + (((u32)(k0 * 2)) ^ xv)) = make_uint2(p01, p23);
        }
        __syncthreads();
    }
}

// ============================================================
// score: 128x128 tile, K=128, 3-pass bf16-split mma.sync
// writes S + St + rowmax/colmax partials
// smem: [Ah 32K][Al 32K][Bh 32K][Bl 32K]; epilogue reuses as 128x132 f32
// ============================================================
#define SC_SMEM 131072
__global__ __launch_bounds__(256, 1) void score_kernel() {
    extern __shared__ u8 sm[];
    const u32 sb = smem_u32(sm);
    const int t = threadIdx.x, lane = t & 31, wid = t >> 5;
    const int wm = wid & 1, wn = wid >> 1;
    const int b = blockIdx.z, mt = blockIdx.y, nt = blockIdx.x;

    {
        const u8* s0 = g_k1pack + ((size_t)(b * 16 + mt) * 2) * 32768;
        const u8* s1 = s0 + 32768;
        const u8* s2 = g_k2pack + ((size_t)(b * 16 + nt) * 2) * 32768;
        const u8* s3 = s2 + 32768;
#pragma unroll
        for (int j = 0; j < 8; j++) {
            const u32 o = (u32)((j * 256 + t) * 16);
            CP_ASYNC16(sb + o, s0 + o);
            CP_ASYNC16(sb + 32768 + o, s1 + o);
            CP_ASYNC16(sb + 65536 + o, s2 + o);
            CP_ASYNC16(sb + 98304 + o, s3 + o);
        }
        CP_COMMIT(); CP_WAIT0();
    }
    __syncthreads();

    float acc[4][4][4];
#pragma unroll
    for (int i = 0; i < 4; i++)
#pragma unroll
        for (int j = 0; j < 4; j++)
#pragma unroll
            for (int q = 0; q < 4; q++) acc[i][j][q] = 0.f;

    const int lr = lane & 15;
#pragma unroll
    for (int ks = 0; ks < 8; ks++) {
        const u32 kcb = (u32)((ks >> 2) * 16384);
        const u32 kb = (u32)(((ks & 3) * 16 + (lane >> 4) * 8) * 2);
        u32 ah[4][4], al[4][4], bh[2][4], bl[2][4];
#pragma unroll
        for (int mf = 0; mf < 4; mf++) {
            const int r = wm * 64 + mf * 16 + lr;
            const u32 ro = kcb + (u32)(r * 128) + (kb ^ ((u32)((r & 7) * 16)));
            ldsm4(ah[mf], sb + ro);
            ldsm4(al[mf], sb + 32768 + ro);
        }
#pragma unroll
        for (int nb = 0; nb < 2; nb++) {
            const int r = wn * 32 + nb * 16 + lr;
            const u32 ro = kcb + (u32)(r * 128) + (kb ^ ((u32)((r & 7) * 16)));
            ldsm4(bh[nb], sb + 65536 + ro);
            ldsm4(bl[nb], sb + 98304 + ro);
        }
#pragma unroll
        for (int mf = 0; mf < 4; mf++)
#pragma unroll
            for (int n8 = 0; n8 < 4; n8++) {
                const int nb = n8 >> 1, i = n8 & 1;
                mma_bf16(acc[mf][n8], ah[mf], bh[nb][i], bh[nb][i + 2]);
                mma_bf16(acc[mf][n8], al[mf], bh[nb][i], bh[nb][i + 2]);
                mma_bf16(acc[mf][n8], ah[mf], bl[nb][i], bl[nb][i + 2]);
            }
    }
    __syncthreads();

    float* smT = (float*)sm;  // 128 x 132
    const int g = lane >> 2, tig = lane & 3;
#pragma unroll
    for (int mf = 0; mf < 4; mf++)
#pragma unroll
        for (int n8 = 0; n8 < 4; n8++) {
            const int r = wm * 64 + mf * 16 + g;
            const int c = wn * 32 + n8 * 8 + tig * 2;
            *(float2*)&smT[r * 132 + c]       = make_float2(acc[mf][n8][0], acc[mf][n8][1]);
            *(float2*)&smT[(r + 8) * 132 + c] = make_float2(acc[mf][n8][2], acc[mf][n8][3]);
        }
    __syncthreads();

    {   // S rows + rowmax partials
        const int r = t >> 1, ch = t & 1;
        float mx = NEG_INF;
        float* Sp = g_S + ((size_t)(b * N_ + mt * 128 + r)) * N_ + nt * 128 + ch * 64;
#pragma unroll
        for (int j = 0; j < 16; j++) {
            float4 v = make_float4(smT[r * 132 + ch * 64 + 4 * j + 0],
                                   smT[r * 132 + ch * 64 + 4 * j + 1],
                                   smT[r * 132 + ch * 64 + 4 * j + 2],
                                   smT[r * 132 + ch * 64 + 4 * j + 3]);
            mx = fmaxf(mx, fmaxf(fmaxf(v.x, v.y), fmaxf(v.z, v.w)));
            *(float4*)(Sp + 4 * j) = v;
        }
        g_rmpart[(size_t)(b * N_ + mt * 128 + r) * 32 + nt * 2 + ch] = mx;
    }
    {   // St rows + colmax partials
        const int c = t >> 1, mh = (t & 1) * 64;
        float mx = NEG_INF;
        float* Tp = g_St + ((size_t)(b * N_ + nt * 128 + c)) * N_ + mt * 128 + mh;
#pragma unroll
        for (int q = 0; q < 16; q++) {
            float4 v = make_float4(smT[(mh + 4 * q + 0) * 132 + c], smT[(mh + 4 * q + 1) * 132 + c],
                                   smT[(mh + 4 * q + 2) * 132 + c], smT[(mh + 4 * q + 3) * 132 + c]);
            mx = fmaxf(mx, fmaxf(fmaxf(v.x, v.y), fmaxf(v.z, v.w)));
            *(float4*)(Tp + 4 * q) = v;
        }
        g_cmpart[(size_t)(b * N_ + nt * 128 + c) * 32 + mt * 2 + (t & 1)] = mx;
    }
}

// ============================================================
// maxreduce: which=0 -> rowmax from rmpart; which=1 -> colmax from cmpart
// (device symbols resolved INSIDE the kernel)
// ============================================================
__global__ void maxreduce_kernel(int which) {
    const float* part = which ? g_cmpart : g_rmpart;
    float* out = which ? g_colmax : g_rowmax;
    const int i = blockIdx.x * 256 + threadIdx.x;
    const float* p = part + (size_t)i * 32;
    float m = p[0];
#pragma unroll
    for (int j = 1; j < 32; j++) m = fmaxf(m, p[j]);
    out[i] = m;
}

// ============================================================
// o kernel: out[b][m0+r][0..255] = sum_k exp(Ssrc[m][k]-ref[m]) * V[n][k] / sum
// 128m x 256n tile, K=2048, fp16 mma, double-buffered
// smem: buf p @ p*49152: [A 16K][B 32K]; red @ 98304 (1KB)
// ============================================================
#define O_SMEM (2 * 49152 + 1024)
__global__ __launch_bounds__(256, 1) void o_kernel(float* __restrict__ out, int which) {
    extern __shared__ u8 sm[];
    const u32 sb = smem_u32(sm);
    const int t = threadIdx.x, lane = t & 31, wid = t >> 5;
    const int wm = wid & 1, wn = wid >> 1;
    const int b = blockIdx.y, m0 = blockIdx.x * 128;
    float* red = (float*)(sm + 98304);

    const float* Ssrc = which ? g_St : g_S;
    const float* refm = which ? g_colmax : g_rowmax;
    const u8*    vp   = which ? g_v1pack : g_v2pack;

    const int arow = t >> 1, akh = (t & 1) * 32;
    const float rm = refm[b * N_ + m0 + arow];
    const float* Srow = Ssrc + ((size_t)(b * N_ + m0 + arow)) * N_;
    const u32 axv = (u32)((arow & 7) * 16);
    float rsum = 0.f;

    float acc[4][8][4];
#pragma unroll
    for (int i = 0; i < 4; i++)
#pragma unroll
        for (int j = 0; j < 8; j++)
#pragma unroll
            for (int q = 0; q < 4; q++) acc[i][j][q] = 0.f;

    // prologue: B chunk 0 -> buf 0
    {
        const u8* src = vp + ((size_t)b * 32 + 0) * 32768 + t * 128;
        const u32 dst = sb + 16384 + (u32)(t * 128);
#pragma unroll
        for (int i = 0; i < 8; i++) CP_ASYNC16(dst + i * 16, src + i * 16);
        CP_COMMIT();
    }

    for (int c = 0; c < 32; c++) {
        const int p = c & 1;
        if (c + 1 < 32) {  // prefetch next B into other buf
            const u8* src = vp + ((size_t)b * 32 + c + 1) * 32768 + t * 128;
            const u32 dst = sb + (u32)((p ^ 1) * 49152 + 16384 + t * 128);
#pragma unroll
            for (int i = 0; i < 8; i++) CP_ASYNC16(dst + i * 16, src + i * 16);
            CP_COMMIT();
        }
        // stage A (exp) for chunk c into buf p
        {
            u8* Ab = sm + p * 49152;
#pragma unroll
            for (int j = 0; j < 8; j++) {
                float4 f = *(const float4*)(Srow + c * 64 + akh + 4 * j);
                float e0 = __expf(f.x - rm), e1 = __expf(f.y - rm);
                float e2 = __expf(f.z - rm), e3 = __expf(f.w - rm);
                rsum += (e0 + e1) + (e2 + e3);
                const u32 off = (u32)(arow * 128) + (((u32)((akh + 4 * j) * 2)) ^ axv);
                *(uint2*)(Ab + off) = make_uint2(f16x2_pack(e0, e1), f16x2_pack(e2, e3));
            }
        }
        if (c + 1 < 32) { CP_WAIT1(); } else { CP_WAIT0(); }
        __syncthreads();
        const u32 Abase = sb + (u32)(p * 49152);
        const u32 Bbase = Abase + 16384;
        const int lr = lane & 15;
#pragma unroll
        for (int ks = 0; ks < 4; ks++) {
            const u32 kb = (u32)((ks * 16 + (lane >> 4) * 8) * 2);
            u32 a[4][4], bb[4][4];
#pragma unroll
            for (int mf = 0; mf < 4; mf++) {
                const int r = wm * 64 + mf * 16 + lr;
                ldsm4(a[mf], Abase + (u32)(r * 128) + (kb ^ ((u32)((r & 7) * 16))));
            }
#pragma unroll
            for (int nb = 0; nb < 4; nb++) {
                const int r = wn * 64 + nb * 16 + lr;
                ldsm4(bb[nb], Bbase + (u32)(r * 128) + (kb ^ ((u32)((r & 7) * 16))));
            }
#pragma unroll
            for (int mf = 0; mf < 4; mf++)
#pragma unroll
                for (int n8 = 0; n8 < 8; n8++) {
                    const int nb = n8 >> 1, i = n8 & 1;
                    mma_f16(acc[mf][n8], a[mf], bb[nb][i], bb[nb][i + 2]);
                }
        }
        __syncthreads();
    }

    red[t] = rsum;
    __syncthreads();
    const int g = lane >> 2, tig = lane & 3;
#pragma unroll
    for (int mf = 0; mf < 4; mf++) {
        const int r0 = wm * 64 + mf * 16 + g;
        const int r1 = r0 + 8;
        const float inv0 = 1.f / (red[2 * r0] + red[2 * r0 + 1]);
        const float inv1 = 1.f / (red[2 * r1] + red[2 * r1 + 1]);
        float* o0 = out + ((size_t)(b * N_ + m0 + r0)) * VD;
        float* o1 = out + ((size_t)(b * N_ + m0 + r1)) * VD;
#pragma unroll
        for (int n8 = 0; n8 < 8; n8++) {
            const int cc = wn * 64 + n8 * 8 + tig * 2;
            *(float2*)(o0 + cc) = make_float2(acc[mf][n8][0] * inv0, acc[mf][n8][1] * inv0);
            *(float2*)(o1 + cc) = make_float2(acc[mf][n8][2] * inv1, acc[mf][n8][3] * inv1);
        }
    }
}

// ============================================================
extern "C" void kernel_launch(void* const* d_in, const int* in_sizes, int n_in,
                              void* d_out, int out_size) {
    (void)in_sizes; (void)n_in; (void)out_size;
    const float* k1 = (const float*)d_in[0];
    const float* k2 = (const float*)d_in[1];
    const float* v1 = (const float*)d_in[2];
    const float* v2 = (const float*)d_in[3];
    const float* W1 = (const float*)d_in[4];
    const float* b1 = (const float*)d_in[5];
    const float* W2 = (const float*)d_in[6];
    const float* b2 = (const float*)d_in[7];
    float* out = (float*)d_out;
    float* o2_out = out;
    float* o1_out = out + (size_t)B_ * N_ * VD;

    cudaFuncSetAttribute(score_kernel, cudaFuncAttributeMaxDynamicSharedMemorySize, SC_SMEM);
    cudaFuncSetAttribute(o_kernel, cudaFuncAttributeMaxDynamicSharedMemorySize, O_SMEM);

    proj_kernel<<<(B_ * N_) / 128, 256>>>(k1, W1, b1, 0);
    proj_kernel<<<(B_ * N_) / 128, 256>>>(k2, W2, b2, 1);
    vpack_kernel<<<dim3(32, B_), 256>>>(v1, 0);
    vpack_kernel<<<dim3(32, B_), 256>>>(v2, 1);

    score_kernel<<<dim3(16, 16, B_), 256, SC_SMEM>>>();

    maxreduce_kernel<<<(B_ * N_) / 256, 256>>>(0);
    maxreduce_kernel<<<(B_ * N_) / 256, 256>>>(1);

    o_kernel<<<dim3(16, B_), 256, O_SMEM>>>(o2_out, 0);
    o_kernel<<<dim3(16, B_), 256, O_SMEM>>>(o1_out, 1);
}

// round 7
// speedup vs baseline: 2.5539x; 1.0350x over previous
#include <cuda_runtime.h>
#include <cuda_fp16.h>
#include <cstdint>
#include <cstddef>

#define B_  8
#define N_  2048
#define KD  256
#define VD  256
#define AD  128
#define NEG_INF (-3.402823466e38f)

typedef unsigned char u8;
typedef unsigned int  u32;

// ------------------- device scratch -------------------
__device__ __align__(16) u8 g_k1pack[(size_t)B_ * 16 * 2 * 32768];   // 8 MB
__device__ __align__(16) u8 g_k2pack[(size_t)B_ * 16 * 2 * 32768];   // 8 MB
__device__ __align__(16) u8 g_v1pack[(size_t)B_ * 32 * 32768];       // 8 MB
__device__ __align__(16) u8 g_v2pack[(size_t)B_ * 32 * 32768];       // 8 MB
__device__ float g_S[(size_t)B_ * N_ * N_];                          // 128 MB
__device__ float g_rmpart[(size_t)B_ * N_ * 32];
__device__ float g_cmpart[(size_t)B_ * N_ * 32];
__device__ float g_rowmax[B_ * N_];
__device__ float g_colmax[B_ * N_];

// ------------------- helpers -------------------
__device__ __forceinline__ u32 smem_u32(const void* p) {
    u32 a;
    asm("{ .reg .u64 t; cvta.to.shared.u64 t, %1; cvt.u32.u64 %0, t; }" : "=r"(a) : "l"(p));
    return a;
}
__device__ __forceinline__ u32 f16x2_pack(float a, float b) {
    u32 r;
    asm("cvt.rn.f16x2.f32 %0, %1, %2;" : "=r"(r) : "f"(b), "f"(a));
    return r;
}
__device__ __forceinline__ void split2(float f0, float f1, u32& hi, u32& lo) {
    u32 h;
    asm("cvt.rn.bf16x2.f32 %0, %1, %2;" : "=r"(h) : "f"(f1), "f"(f0));
    float h0 = __uint_as_float(h << 16);
    float h1 = __uint_as_float(h & 0xFFFF0000u);
    u32 l;
    asm("cvt.rn.bf16x2.f32 %0, %1, %2;" : "=r"(l) : "f"(f1 - h1), "f"(f0 - h0));
    hi = h; lo = l;
}
__device__ __forceinline__ void mma_bf16(float* c, const u32* a, u32 b0, u32 b1) {
    asm volatile(
        "mma.sync.aligned.m16n8k16.row.col.f32.bf16.bf16.f32 "
        "{%0,%1,%2,%3}, {%4,%5,%6,%7}, {%8,%9}, {%0,%1,%2,%3};"
        : "+f"(c[0]), "+f"(c[1]), "+f"(c[2]), "+f"(c[3])
        : "r"(a[0]), "r"(a[1]), "r"(a[2]), "r"(a[3]), "r"(b0), "r"(b1));
}
__device__ __forceinline__ void mma_f16(float* c, const u32* a, u32 b0, u32 b1) {
    asm volatile(
        "mma.sync.aligned.m16n8k16.row.col.f32.f16.f16.f32 "
        "{%0,%1,%2,%3}, {%4,%5,%6,%7}, {%8,%9}, {%0,%1,%2,%3};"
        : "+f"(c[0]), "+f"(c[1]), "+f"(c[2]), "+f"(c[3])
        : "r"(a[0]), "r"(a[1]), "r"(a[2]), "r"(a[3]), "r"(b0), "r"(b1));
}
__device__ __forceinline__ void ldsm4(u32* r, u32 addr) {
    asm volatile("ldmatrix.sync.aligned.m8n8.x4.shared.b16 {%0,%1,%2,%3}, [%4];"
                 : "=r"(r[0]), "=r"(r[1]), "=r"(r[2]), "=r"(r[3]) : "r"(addr));
}
#define CP_ASYNC16(dst, src)                                                \
    asm volatile("cp.async.cg.shared.global [%0], [%1], 16;"                \
                 :: "r"(dst), "l"(__cvta_generic_to_global(src)))
#define CP_COMMIT()  asm volatile("cp.async.commit_group;")
#define CP_WAITG(n)  asm volatile("cp.async.wait_group %0;" :: "n"(n))

// ============================================================
// proj (tensor): C = A[M,256] @ W[256,128] + bias -> split bf16 pack
// CTA: 128m x 128n, K in 4 chunks of 64, 3-pass bf16-split mma
// ============================================================
#define P_SMEM 99840
__global__ __launch_bounds__(256) void proj_kernel(const float* __restrict__ A,
                                                   const float* __restrict__ W,
                                                   const float* __restrict__ bias,
                                                   int which) {
    extern __shared__ u8 sm[];
    const u32 sb = smem_u32(sm);
    float* Wst = (float*)(sm + 65536);          // [64][132]
    float* bc  = (float*)(sm + 99328);          // [128]
    const int t = threadIdx.x, lane = t & 31, wid = t >> 5;
    const int wm = wid & 1, wn = wid >> 1;
    const int m0 = blockIdx.x * 128;
    if (t < 128) bc[t] = bias[t];

    float acc[4][4][4];
#pragma unroll
    for (int i = 0; i < 4; i++)
#pragma unroll
        for (int j = 0; j < 4; j++)
#pragma unroll
            for (int q = 0; q < 4; q++) acc[i][j][q] = 0.f;

    const int lr = lane & 15;
    for (int kc = 0; kc < 4; kc++) {
        __syncthreads();
        // stage A chunk
        {
            const int m = t >> 1, kh = (t & 1) * 32;
            const float* Ar = A + (size_t)(m0 + m) * KD + kc * 64 + kh;
            const u32 xv = (u32)((m & 7) * 16);
#pragma unroll
            for (int j = 0; j < 8; j++) {
                float4 f = *(const float4*)(Ar + 4 * j);
                u32 h01, l01, h23, l23;
                split2(f.x, f.y, h01, l01); split2(f.z, f.w, h23, l23);
                const u32 off = (u32)(m * 128) + (((u32)((kh + 4 * j) * 2)) ^ xv);
                *(uint2*)(sm + off)         = make_uint2(h01, h23);
                *(uint2*)(sm + 16384 + off) = make_uint2(l01, l23);
            }
        }
        // stage W chunk [64k][128n] coalesced
        {
            const int k = t >> 2, ns = (t & 3) * 32;
            const float* Wr = W + (size_t)(kc * 64 + k) * AD + ns;
#pragma unroll
            for (int j = 0; j < 8; j++)
                *(float4*)&Wst[k * 132 + ns + 4 * j] = *(const float4*)(Wr + 4 * j);
        }
        __syncthreads();
        // transpose-pack W
        {
            const int n = t >> 1, kh = (t & 1) * 32;
            const u32 xv = (u32)((n & 7) * 16);
#pragma unroll
            for (int jq = 0; jq < 8; jq++) {
                float w0 = Wst[(kh + 4 * jq + 0) * 132 + n];
                float w1 = Wst[(kh + 4 * jq + 1) * 132 + n];
                float w2 = Wst[(kh + 4 * jq + 2) * 132 + n];
                float w3 = Wst[(kh + 4 * jq + 3) * 132 + n];
                u32 h01, l01, h23, l23;
                split2(w0, w1, h01, l01); split2(w2, w3, h23, l23);
                const u32 off = (u32)(n * 128) + (((u32)((kh + 4 * jq) * 2)) ^ xv);
                *(uint2*)(sm + 32768 + off) = make_uint2(h01, h23);
                *(uint2*)(sm + 49152 + off) = make_uint2(l01, l23);
            }
        }
        __syncthreads();
#pragma unroll
        for (int ks = 0; ks < 4; ks++) {
            const u32 kb = (u32)((ks * 16 + (lane >> 4) * 8) * 2);
            u32 ah[4][4], al[4][4], bh[2][4], bl[2][4];
#pragma unroll
            for (int mf = 0; mf < 4; mf++) {
                const int r = wm * 64 + mf * 16 + lr;
                const u32 ro = (u32)(r * 128) + (kb ^ ((u32)((r & 7) * 16)));
                ldsm4(ah[mf], sb + ro);
                ldsm4(al[mf], sb + 16384 + ro);
            }
#pragma unroll
            for (int nb = 0; nb < 2; nb++) {
                const int r = wn * 32 + nb * 16 + lr;
                const u32 ro = (u32)(r * 128) + (kb ^ ((u32)((r & 7) * 16)));
                ldsm4(bh[nb], sb + 32768 + ro);
                ldsm4(bl[nb], sb + 49152 + ro);
            }
#pragma unroll
            for (int mf = 0; mf < 4; mf++)
#pragma unroll
                for (int n8 = 0; n8 < 4; n8++) {
                    const int nb = n8 >> 1, i = n8 & 1;
                    mma_bf16(acc[mf][n8], ah[mf], bh[nb][i], bh[nb][i + 2]);
                    mma_bf16(acc[mf][n8], al[mf], bh[nb][i], bh[nb][i + 2]);
                    mma_bf16(acc[mf][n8], ah[mf], bl[nb][i], bl[nb][i + 2]);
                }
        }
    }
    __syncthreads();
    float* smT = (float*)sm;  // 128 x 132
    const int g = lane >> 2, tig = lane & 3;
#pragma unroll
    for (int mf = 0; mf < 4; mf++)
#pragma unroll
        for (int n8 = 0; n8 < 4; n8++) {
            const int r = wm * 64 + mf * 16 + g;
            const int c = wn * 32 + n8 * 8 + tig * 2;
            const float b0 = bc[c], b1 = bc[c + 1];
            *(float2*)&smT[r * 132 + c]       = make_float2(acc[mf][n8][0] + b0, acc[mf][n8][1] + b1);
            *(float2*)&smT[(r + 8) * 132 + c] = make_float2(acc[mf][n8][2] + b0, acc[mf][n8][3] + b1);
        }
    __syncthreads();
    {
        const int b_ = m0 / N_, mt = (m0 % N_) / 128;
        u8* hibase = (which ? g_k2pack : g_k1pack) + ((size_t)(b_ * 16 + mt) * 2) * 32768;
        u8* lobase = hibase + 32768;
        const int row = t >> 1, ch = t & 1;
        const u32 xv = (u32)((row & 7) * 16);
#pragma unroll
        for (int j = 0; j < 16; j++) {
            float f0 = smT[row * 132 + ch * 64 + 4 * j + 0];
            float f1 = smT[row * 132 + ch * 64 + 4 * j + 1];
            float f2 = smT[row * 132 + ch * 64 + 4 * j + 2];
            float f3 = smT[row * 132 + ch * 64 + 4 * j + 3];
            u32 h01, l01, h23, l23;
            split2(f0, f1, h01, l01); split2(f2, f3, h23, l23);
            const u32 off = (u32)(ch * 16384 + row * 128) + (((u32)(8 * j)) ^ xv);
            *(uint2*)(hibase + off) = make_uint2(h01, h23);
            *(uint2*)(lobase + off) = make_uint2(l01, l23);
        }
    }
}

// ============================================================
// vpack: both V's in one launch (z = which)
// ============================================================
__global__ __launch_bounds__(256) void vpack_kernel(const float* __restrict__ v1,
                                                    const float* __restrict__ v2) {
    __shared__ float sv[64][68];
    const int which = blockIdx.z;
    const float* v = which ? v2 : v1;
    u8* dst = which ? g_v2pack : g_v1pack;
    const int b = blockIdx.y, kc = blockIdx.x;
    const int t = threadIdx.x;
    u8* tile = dst + ((size_t)b * 32 + kc) * 32768;
    for (int dc = 0; dc < 4; dc++) {
#pragma unroll
        for (int i = 0; i < 4; i++) {
            const int q = t + i * 256;
            const int kr = q >> 4, dl = (q & 15) * 4;
            float4 f = *(const float4*)(v + ((size_t)b * N_ + kc * 64 + kr) * VD + dc * 64 + dl);
            sv[dl + 0][kr] = f.x; sv[dl + 1][kr] = f.y;
            sv[dl + 2][kr] = f.z; sv[dl + 3][kr] = f.w;
        }
        __syncthreads();
        const int dl = t >> 2, q = t & 3;
        const int row = dc * 64 + dl;
        const u32 xv = (u32)((row & 7) * 16);
#pragma unroll
        for (int j = 0; j < 4; j++) {
            const int k0 = q * 16 + j * 4;
            u32 p01 = f16x2_pack(sv[dl][k0 + 0], sv[dl][k0 + 1]);
            u32 p23 = f16x2_pack(sv[dl][k0 + 2], sv[dl][k0 + 3]);
            *(uint2*)(tile + row * 128 + (((u32)(k0 * 2)) ^ xv)) = make_uint2(p01, p23);
        }
        __syncthreads();
    }
}

// ============================================================
// score: 128x128 tile, K=128, 3-pass bf16-split. Writes S + row/col max partials.
// ============================================================
#define SC_SMEM 131072
__global__ __launch_bounds__(256, 1) void score_kernel() {
    extern __shared__ u8 sm[];
    const u32 sb = smem_u32(sm);
    const int t = threadIdx.x, lane = t & 31, wid = t >> 5;
    const int wm = wid & 1, wn = wid >> 1;
    const int b = blockIdx.z, mt = blockIdx.y, nt = blockIdx.x;

    {
        const u8* s0 = g_k1pack + ((size_t)(b * 16 + mt) * 2) * 32768;
        const u8* s1 = s0 + 32768;
        const u8* s2 = g_k2pack + ((size_t)(b * 16 + nt) * 2) * 32768;
        const u8* s3 = s2 + 32768;
#pragma unroll
        for (int j = 0; j < 8; j++) {
            const u32 o = (u32)((j * 256 + t) * 16);
            CP_ASYNC16(sb + o, s0 + o);
            CP_ASYNC16(sb + 32768 + o, s1 + o);
            CP_ASYNC16(sb + 65536 + o, s2 + o);
            CP_ASYNC16(sb + 98304 + o, s3 + o);
        }
        CP_COMMIT(); CP_WAITG(0);
    }
    __syncthreads();

    float acc[4][4][4];
#pragma unroll
    for (int i = 0; i < 4; i++)
#pragma unroll
        for (int j = 0; j < 4; j++)
#pragma unroll
            for (int q = 0; q < 4; q++) acc[i][j][q] = 0.f;

    const int lr = lane & 15;
#pragma unroll
    for (int ks = 0; ks < 8; ks++) {
        const u32 kcb = (u32)((ks >> 2) * 16384);
        const u32 kb = (u32)(((ks & 3) * 16 + (lane >> 4) * 8) * 2);
        u32 ah[4][4], al[4][4], bh[2][4], bl[2][4];
#pragma unroll
        for (int mf = 0; mf < 4; mf++) {
            const int r = wm * 64 + mf * 16 + lr;
            const u32 ro = kcb + (u32)(r * 128) + (kb ^ ((u32)((r & 7) * 16)));
            ldsm4(ah[mf], sb + ro);
            ldsm4(al[mf], sb + 32768 + ro);
        }
#pragma unroll
        for (int nb = 0; nb < 2; nb++) {
            const int r = wn * 32 + nb * 16 + lr;
            const u32 ro = kcb + (u32)(r * 128) + (kb ^ ((u32)((r & 7) * 16)));
            ldsm4(bh[nb], sb + 65536 + ro);
            ldsm4(bl[nb], sb + 98304 + ro);
        }
#pragma unroll
        for (int mf = 0; mf < 4; mf++)
#pragma unroll
            for (int n8 = 0; n8 < 4; n8++) {
                const int nb = n8 >> 1, i = n8 & 1;
                mma_bf16(acc[mf][n8], ah[mf], bh[nb][i], bh[nb][i + 2]);
                mma_bf16(acc[mf][n8], al[mf], bh[nb][i], bh[nb][i + 2]);
                mma_bf16(acc[mf][n8], ah[mf], bl[nb][i], bl[nb][i + 2]);
            }
    }
    __syncthreads();

    float* smT = (float*)sm;  // 128 x 132
    const int g = lane >> 2, tig = lane & 3;
#pragma unroll
    for (int mf = 0; mf < 4; mf++)
#pragma unroll
        for (int n8 = 0; n8 < 4; n8++) {
            const int r = wm * 64 + mf * 16 + g;
            const int c = wn * 32 + n8 * 8 + tig * 2;
            *(float2*)&smT[r * 132 + c]       = make_float2(acc[mf][n8][0], acc[mf][n8][1]);
            *(float2*)&smT[(r + 8) * 132 + c] = make_float2(acc[mf][n8][2], acc[mf][n8][3]);
        }
    __syncthreads();

    {   // S rows + rowmax partials
        const int r = t >> 1, ch = t & 1;
        float mx = NEG_INF;
        float* Sp = g_S + ((size_t)(b * N_ + mt * 128 + r)) * N_ + nt * 128 + ch * 64;
#pragma unroll
        for (int j = 0; j < 16; j++) {
            float4 v = make_float4(smT[r * 132 + ch * 64 + 4 * j + 0],
                                   smT[r * 132 + ch * 64 + 4 * j + 1],
                                   smT[r * 132 + ch * 64 + 4 * j + 2],
                                   smT[r * 132 + ch * 64 + 4 * j + 3]);
            mx = fmaxf(mx, fmaxf(fmaxf(v.x, v.y), fmaxf(v.z, v.w)));
            *(float4*)(Sp + 4 * j) = v;
        }
        g_rmpart[(size_t)(b * N_ + mt * 128 + r) * 32 + nt * 2 + ch] = mx;
    }
    {   // colmax partials (no St store)
        const int c = t >> 1, mh = (t & 1) * 64;
        float mx = NEG_INF;
#pragma unroll
        for (int q = 0; q < 64; q++) mx = fmaxf(mx, smT[(mh + q) * 132 + c]);
        g_cmpart[(size_t)(b * N_ + nt * 128 + c) * 32 + mt * 2 + (t & 1)] = mx;
    }
}

// ============================================================
__global__ void maxreduce_kernel() {
    const int which = blockIdx.y;
    const float* part = which ? g_cmpart : g_rmpart;
    float* out = which ? g_colmax : g_rowmax;
    const int i = blockIdx.x * 256 + threadIdx.x;
    const float* p = part + (size_t)i * 32;
    float m = p[0];
#pragma unroll
    for (int j = 1; j < 32; j++) m = fmaxf(m, p[j]);
    out[i] = m;
}

// ============================================================
// o kernel (fused o1+o2, z = which): 64m x 256n tile, K=2048, fp16 mma
// smem: V[2]@0 | Sst[2]@64K (pitch 272B) | Af16@100352 | red@108544
// ============================================================
#define O_SMEM 109568
__global__ __launch_bounds__(256) void o_kernel(float* __restrict__ o2_out,
                                                float* __restrict__ o1_out) {
    extern __shared__ u8 sm[];
    const u32 sb = smem_u32(sm);
    const int t = threadIdx.x, lane = t & 31, wid = t >> 5;
    const int wm = wid & 1, wn = wid >> 1;
    const int which = blockIdx.z;
    const int b = blockIdx.y, m0 = blockIdx.x * 64;
    float* red = (float*)(sm + 108544);

    const float* refm = which ? g_colmax : g_rowmax;
    const u8*    vp   = which ? g_v1pack : g_v2pack;
    float* outp = which ? o1_out : o2_out;
    const float* Sb = g_S + (size_t)b * N_ * N_;

    const u32 VB = sb, SST = sb + 65536, AF = sb + 100352;

    const int pm = t >> 2, pq = (t & 3) * 16;
    const float rm = refm[b * N_ + m0 + pm];
    const u32 axv = (u32)((pm & 7) * 16);

    float acc[2][8][4];
#pragma unroll
    for (int i = 0; i < 2; i++)
#pragma unroll
        for (int j = 0; j < 8; j++)
#pragma unroll
            for (int q = 0; q < 4; q++) acc[i][j][q] = 0.f;

    auto issue = [&](int cc) {
        const int p = cc & 1;
        {   // V: 32KB straight copy
            const u8* src = vp + ((size_t)b * 32 + cc) * 32768 + t * 128;
            const u32 dst = VB + (u32)(p * 32768 + t * 128);
#pragma unroll
            for (int i = 0; i < 8; i++) CP_ASYNC16(dst + i * 16, src + i * 16);
        }
        {   // S: 64 rows x 256B, pitch 272
            const int r = t >> 2, q = (t & 3) * 64;
            const float* src = which
                ? (Sb + (size_t)(cc * 64 + r) * N_ + m0)
                : (Sb + (size_t)(m0 + r) * N_ + cc * 64);
            const u32 dst = SST + (u32)(p * 17408 + r * 272 + q);
#pragma unroll
            for (int i = 0; i < 4; i++) CP_ASYNC16(dst + i * 16, (const u8*)src + q + i * 16);
        }
        CP_COMMIT();
    };

    issue(0);
    float rsum = 0.f;
    const int lr = lane & 15;

    for (int c = 0; c < 32; c++) {
        const int p = c & 1;
        if (c + 1 < 32) { issue(c + 1); CP_WAITG(1); }
        else            { CP_WAITG(0); }
        __syncthreads();
        // pack A: exp + fp16
        {
            const float* st = (const float*)(sm + 65536 + p * 17408);
            float e[16];
            if (which == 0) {
                const float* rowp = st + pm * 68 + pq;
#pragma unroll
                for (int j = 0; j < 16; j += 4) {
                    float4 f = *(const float4*)(rowp + j);
                    e[j] = __expf(f.x - rm); e[j + 1] = __expf(f.y - rm);
                    e[j + 2] = __expf(f.z - rm); e[j + 3] = __expf(f.w - rm);
                }
            } else {
#pragma unroll
                for (int j = 0; j < 16; j++)
                    e[j] = __expf(st[(pq + j) * 68 + pm] - rm);
            }
#pragma unroll
            for (int j = 0; j < 16; j++) rsum += e[j];
#pragma unroll
            for (int j = 0; j < 4; j++) {
                u32 p01 = f16x2_pack(e[4 * j + 0], e[4 * j + 1]);
                u32 p23 = f16x2_pack(e[4 * j + 2], e[4 * j + 3]);
                const u32 off = (u32)(pm * 128) + (((u32)((pq + 4 * j) * 2)) ^ axv);
                *(uint2*)(sm + 100352 + off) = make_uint2(p01, p23);
            }
        }
        __syncthreads();
        // mma: A 64x64 f16, B (V) 256x64 f16
#pragma unroll
        for (int ks = 0; ks < 4; ks++) {
            const u32 kb = (u32)((ks * 16 + (lane >> 4) * 8) * 2);
            u32 a[2][4], bb[4][4];
#pragma unroll
            for (int mf = 0; mf < 2; mf++) {
                const int r = wm * 32 + mf * 16 + lr;
                ldsm4(a[mf], AF + (u32)(r * 128) + (kb ^ ((u32)((r & 7) * 16))));
            }
#pragma unroll
            for (int nb = 0; nb < 4; nb++) {
                const int r = wn * 64 + nb * 16 + lr;
                ldsm4(bb[nb], VB + (u32)(p * 32768 + r * 128) + (kb ^ ((u32)((r & 7) * 16))));
            }
#pragma unroll
            for (int mf = 0; mf < 2; mf++)
#pragma unroll
                for (int n8 = 0; n8 < 8; n8++) {
                    const int nb = n8 >> 1, i = n8 & 1;
                    mma_f16(acc[mf][n8], a[mf], bb[nb][i], bb[nb][i + 2]);
                }
        }
        // RACE FIX (R6 bug): all warps must finish reading V[p]/Sst[p] before any
        // thread loops around and issues cp.async for chunk c+2 into buffer p.
        __syncthreads();
    }
    red[t] = rsum;
    __syncthreads();
    const int g = lane >> 2, tig = lane & 3;
#pragma unroll
    for (int mf = 0; mf < 2; mf++) {
        const int r0 = wm * 32 + mf * 16 + g;
        const int r1 = r0 + 8;
        const float inv0 = 1.f / (red[4 * r0] + red[4 * r0 + 1] + red[4 * r0 + 2] + red[4 * r0 + 3]);
        const float inv1 = 1.f / (red[4 * r1] + red[4 * r1 + 1] + red[4 * r1 + 2] + red[4 * r1 + 3]);
        float* po0 = outp + ((size_t)(b * N_ + m0 + r0)) * VD;
        float* po1 = outp + ((size_t)(b * N_ + m0 + r1)) * VD;
#pragma unroll
        for (int n8 = 0; n8 < 8; n8++) {
            const int cc = wn * 64 + n8 * 8 + tig * 2;
            *(float2*)(po0 + cc) = make_float2(acc[mf][n8][0] * inv0, acc[mf][n8][1] * inv0);
            *(float2*)(po1 + cc) = make_float2(acc[mf][n8][2] * inv1, acc[mf][n8][3] * inv1);
        }
    }
}

// ============================================================
extern "C" void kernel_launch(void* const* d_in, const int* in_sizes, int n_in,
                              void* d_out, int out_size) {
    (void)in_sizes; (void)n_in; (void)out_size;
    const float* k1 = (const float*)d_in[0];
    const float* k2 = (const float*)d_in[1];
    const float* v1 = (const float*)d_in[2];
    const float* v2 = (const float*)d_in[3];
    const float* W1 = (const float*)d_in[4];
    const float* b1 = (const float*)d_in[5];
    const float* W2 = (const float*)d_in[6];
    const float* b2 = (const float*)d_in[7];
    float* out = (float*)d_out;
    float* o2_out = out;
    float* o1_out = out + (size_t)B_ * N_ * VD;

    cudaFuncSetAttribute(proj_kernel, cudaFuncAttributeMaxDynamicSharedMemorySize, P_SMEM);
    cudaFuncSetAttribute(score_kernel, cudaFuncAttributeMaxDynamicSharedMemorySize, SC_SMEM);
    cudaFuncSetAttribute(o_kernel, cudaFuncAttributeMaxDynamicSharedMemorySize, O_SMEM);

    proj_kernel<<<(B_ * N_) / 128, 256, P_SMEM>>>(k1, W1, b1, 0);
    proj_kernel<<<(B_ * N_) / 128, 256, P_SMEM>>>(k2, W2, b2, 1);
    vpack_kernel<<<dim3(32, B_, 2), 256>>>(v1, v2);

    score_kernel<<<dim3(16, 16, B_), 256, SC_SMEM>>>();

    maxreduce_kernel<<<dim3((B_ * N_) / 256, 2), 256>>>();

    o_kernel<<<dim3(32, B_, 2), 256, O_SMEM>>>(o2_out, o1_out);
}

// round 9
// speedup vs baseline: 2.9406x; 1.1514x over previous
#include <cuda_runtime.h>
#include <cuda_fp16.h>
#include <cstdint>
#include <cstddef>

#define B_  8
#define N_  2048
#define KD  256
#define VD  256
#define AD  128
#define NEG_INF (-3.402823466e38f)

typedef unsigned char u8;
typedef unsigned int  u32;

// ------------------- device scratch -------------------
__device__ __align__(16) u8 g_k1pack[(size_t)B_ * 16 * 2 * 32768];   // 8 MB
__device__ __align__(16) u8 g_k2pack[(size_t)B_ * 16 * 2 * 32768];   // 8 MB
__device__ __align__(16) u8 g_v1pack[(size_t)B_ * 32 * 32768];       // 8 MB
__device__ __align__(16) u8 g_v2pack[(size_t)B_ * 32 * 32768];       // 8 MB
__device__ float g_S[(size_t)B_ * N_ * N_];                          // 128 MB
__device__ float g_rmpart[(size_t)B_ * N_ * 64];                     // 4 MB
__device__ float g_cmpart[(size_t)B_ * N_ * 32];                     // 2 MB
__device__ float g_rowmax[B_ * N_];
__device__ float g_colmax[B_ * N_];

// ------------------- helpers -------------------
__device__ __forceinline__ u32 smem_u32(const void* p) {
    u32 a;
    asm("{ .reg .u64 t; cvta.to.shared.u64 t, %1; cvt.u32.u64 %0, t; }" : "=r"(a) : "l"(p));
    return a;
}
__device__ __forceinline__ u32 f16x2_pack(float a, float b) {
    u32 r;
    asm("cvt.rn.f16x2.f32 %0, %1, %2;" : "=r"(r) : "f"(b), "f"(a));
    return r;
}
__device__ __forceinline__ void split2(float f0, float f1, u32& hi, u32& lo) {
    u32 h;
    asm("cvt.rn.bf16x2.f32 %0, %1, %2;" : "=r"(h) : "f"(f1), "f"(f0));
    float h0 = __uint_as_float(h << 16);
    float h1 = __uint_as_float(h & 0xFFFF0000u);
    u32 l;
    asm("cvt.rn.bf16x2.f32 %0, %1, %2;" : "=r"(l) : "f"(f1 - h1), "f"(f0 - h0));
    hi = h; lo = l;
}
__device__ __forceinline__ void mma_bf16(float* c, const u32* a, u32 b0, u32 b1) {
    asm volatile(
        "mma.sync.aligned.m16n8k16.row.col.f32.bf16.bf16.f32 "
        "{%0,%1,%2,%3}, {%4,%5,%6,%7}, {%8,%9}, {%0,%1,%2,%3};"
        : "+f"(c[0]), "+f"(c[1]), "+f"(c[2]), "+f"(c[3])
        : "r"(a[0]), "r"(a[1]), "r"(a[2]), "r"(a[3]), "r"(b0), "r"(b1));
}
__device__ __forceinline__ void mma_f16(float* c, const u32* a, u32 b0, u32 b1) {
    asm volatile(
        "mma.sync.aligned.m16n8k16.row.col.f32.f16.f16.f32 "
        "{%0,%1,%2,%3}, {%4,%5,%6,%7}, {%8,%9}, {%0,%1,%2,%3};"
        : "+f"(c[0]), "+f"(c[1]), "+f"(c[2]), "+f"(c[3])
        : "r"(a[0]), "r"(a[1]), "r"(a[2]), "r"(a[3]), "r"(b0), "r"(b1));
}
__device__ __forceinline__ void ldsm4(u32* r, u32 addr) {
    asm volatile("ldmatrix.sync.aligned.m8n8.x4.shared.b16 {%0,%1,%2,%3}, [%4];"
                 : "=r"(r[0]), "=r"(r[1]), "=r"(r[2]), "=r"(r[3]) : "r"(addr));
}
#define CP_ASYNC16(dst, src)                                                \
    asm volatile("cp.async.cg.shared.global [%0], [%1], 16;"                \
                 :: "r"(dst), "l"(__cvta_generic_to_global(src)))
#define CP_COMMIT()  asm volatile("cp.async.commit_group;")
#define CP_WAITG(n)  asm volatile("cp.async.wait_group %0;" :: "n"(n))

// ============================================================
// proj (merged, blockIdx.y = which): C = A[M,256] @ W + bias -> split bf16 pack
// ============================================================
#define P_SMEM 99840
__global__ __launch_bounds__(256) void proj_kernel(const float* __restrict__ k1,
                                                   const float* __restrict__ W1,
                                                   const float* __restrict__ b1v,
                                                   const float* __restrict__ k2,
                                                   const float* __restrict__ W2,
                                                   const float* __restrict__ b2v) {
    extern __shared__ u8 sm[];
    const u32 sb = smem_u32(sm);
    float* Wst = (float*)(sm + 65536);          // [64][132]
    float* bc  = (float*)(sm + 99328);          // [128]
    const int which = blockIdx.y;
    const float* A = which ? k2 : k1;
    const float* W = which ? W2 : W1;
    const float* bias = which ? b2v : b1v;
    const int t = threadIdx.x, lane = t & 31, wid = t >> 5;
    const int wm = wid & 1, wn = wid >> 1;
    const int m0 = blockIdx.x * 128;
    if (t < 128) bc[t] = bias[t];

    float acc[4][4][4];
#pragma unroll
    for (int i = 0; i < 4; i++)
#pragma unroll
        for (int j = 0; j < 4; j++)
#pragma unroll
            for (int q = 0; q < 4; q++) acc[i][j][q] = 0.f;

    const int lr = lane & 15;
    for (int kc = 0; kc < 4; kc++) {
        __syncthreads();
        {   // stage A chunk (split bf16)
            const int m = t >> 1, kh = (t & 1) * 32;
            const float* Ar = A + (size_t)(m0 + m) * KD + kc * 64 + kh;
            const u32 xv = (u32)((m & 7) * 16);
#pragma unroll
            for (int j = 0; j < 8; j++) {
                float4 f = *(const float4*)(Ar + 4 * j);
                u32 h01, l01, h23, l23;
                split2(f.x, f.y, h01, l01); split2(f.z, f.w, h23, l23);
                const u32 off = (u32)(m * 128) + (((u32)((kh + 4 * j) * 2)) ^ xv);
                *(uint2*)(sm + off)         = make_uint2(h01, h23);
                *(uint2*)(sm + 16384 + off) = make_uint2(l01, l23);
            }
        }
        {   // stage W chunk coalesced
            const int k = t >> 2, ns = (t & 3) * 32;
            const float* Wr = W + (size_t)(kc * 64 + k) * AD + ns;
#pragma unroll
            for (int j = 0; j < 8; j++)
                *(float4*)&Wst[k * 132 + ns + 4 * j] = *(const float4*)(Wr + 4 * j);
        }
        __syncthreads();
        {   // transpose-pack W
            const int n = t >> 1, kh = (t & 1) * 32;
            const u32 xv = (u32)((n & 7) * 16);
#pragma unroll
            for (int jq = 0; jq < 8; jq++) {
                float w0 = Wst[(kh + 4 * jq + 0) * 132 + n];
                float w1 = Wst[(kh + 4 * jq + 1) * 132 + n];
                float w2 = Wst[(kh + 4 * jq + 2) * 132 + n];
                float w3 = Wst[(kh + 4 * jq + 3) * 132 + n];
                u32 h01, l01, h23, l23;
                split2(w0, w1, h01, l01); split2(w2, w3, h23, l23);
                const u32 off = (u32)(n * 128) + (((u32)((kh + 4 * jq) * 2)) ^ xv);
                *(uint2*)(sm + 32768 + off) = make_uint2(h01, h23);
                *(uint2*)(sm + 49152 + off) = make_uint2(l01, l23);
            }
        }
        __syncthreads();
#pragma unroll
        for (int ks = 0; ks < 4; ks++) {
            const u32 kb = (u32)((ks * 16 + (lane >> 4) * 8) * 2);
            u32 ah[4][4], al[4][4], bh[2][4], bl[2][4];
#pragma unroll
            for (int mf = 0; mf < 4; mf++) {
                const int r = wm * 64 + mf * 16 + lr;
                const u32 ro = (u32)(r * 128) + (kb ^ ((u32)((r & 7) * 16)));
                ldsm4(ah[mf], sb + ro);
                ldsm4(al[mf], sb + 16384 + ro);
            }
#pragma unroll
            for (int nb = 0; nb < 2; nb++) {
                const int r = wn * 32 + nb * 16 + lr;
                const u32 ro = (u32)(r * 128) + (kb ^ ((u32)((r & 7) * 16)));
                ldsm4(bh[nb], sb + 32768 + ro);
                ldsm4(bl[nb], sb + 49152 + ro);
            }
#pragma unroll
            for (int mf = 0; mf < 4; mf++)
#pragma unroll
                for (int n8 = 0; n8 < 4; n8++) {
                    const int nb = n8 >> 1, i = n8 & 1;
                    mma_bf16(acc[mf][n8], ah[mf], bh[nb][i], bh[nb][i + 2]);
                    mma_bf16(acc[mf][n8], al[mf], bh[nb][i], bh[nb][i + 2]);
                    mma_bf16(acc[mf][n8], ah[mf], bl[nb][i], bl[nb][i + 2]);
                }
        }
    }
    __syncthreads();
    float* smT = (float*)sm;  // 128 x 132
    const int g = lane >> 2, tig = lane & 3;
#pragma unroll
    for (int mf = 0; mf < 4; mf++)
#pragma unroll
        for (int n8 = 0; n8 < 4; n8++) {
            const int r = wm * 64 + mf * 16 + g;
            const int c = wn * 32 + n8 * 8 + tig * 2;
            const float b0 = bc[c], b1 = bc[c + 1];
            *(float2*)&smT[r * 132 + c]       = make_float2(acc[mf][n8][0] + b0, acc[mf][n8][1] + b1);
            *(float2*)&smT[(r + 8) * 132 + c] = make_float2(acc[mf][n8][2] + b0, acc[mf][n8][3] + b1);
        }
    __syncthreads();
    {
        const int b_ = m0 / N_, mt = (m0 % N_) / 128;
        u8* hibase = (which ? g_k2pack : g_k1pack) + ((size_t)(b_ * 16 + mt) * 2) * 32768;
        u8* lobase = hibase + 32768;
        const int row = t >> 1, ch = t & 1;
        const u32 xv = (u32)((row & 7) * 16);
#pragma unroll
        for (int j = 0; j < 16; j++) {
            float f0 = smT[row * 132 + ch * 64 + 4 * j + 0];
            float f1 = smT[row * 132 + ch * 64 + 4 * j + 1];
            float f2 = smT[row * 132 + ch * 64 + 4 * j + 2];
            float f3 = smT[row * 132 + ch * 64 + 4 * j + 3];
            u32 h01, l01, h23, l23;
            split2(f0, f1, h01, l01); split2(f2, f3, h23, l23);
            const u32 off = (u32)(ch * 16384 + row * 128) + (((u32)(8 * j)) ^ xv);
            *(uint2*)(hibase + off) = make_uint2(h01, h23);
            *(uint2*)(lobase + off) = make_uint2(l01, l23);
        }
    }
}

// ============================================================
// vpack: both V's in one launch (z = which)
// ============================================================
__global__ __launch_bounds__(256) void vpack_kernel(const float* __restrict__ v1,
                                                    const float* __restrict__ v2) {
    __shared__ float sv[64][68];
    const int which = blockIdx.z;
    const float* v = which ? v2 : v1;
    u8* dst = which ? g_v2pack : g_v1pack;
    const int b = blockIdx.y, kc = blockIdx.x;
    const int t = threadIdx.x;
    u8* tile = dst + ((size_t)b * 32 + kc) * 32768;
    for (int dc = 0; dc < 4; dc++) {
#pragma unroll
        for (int i = 0; i < 4; i++) {
            const int q = t + i * 256;
            const int kr = q >> 4, dl = (q & 15) * 4;
            float4 f = *(const float4*)(v + ((size_t)b * N_ + kc * 64 + kr) * VD + dc * 64 + dl);
            sv[dl + 0][kr] = f.x; sv[dl + 1][kr] = f.y;
            sv[dl + 2][kr] = f.z; sv[dl + 3][kr] = f.w;
        }
        __syncthreads();
        const int dl = t >> 2, q = t & 3;
        const int row = dc * 64 + dl;
        const u32 xv = (u32)((row & 7) * 16);
#pragma unroll
        for (int j = 0; j < 4; j++) {
            const int k0 = q * 16 + j * 4;
            u32 p01 = f16x2_pack(sv[dl][k0 + 0], sv[dl][k0 + 1]);
            u32 p23 = f16x2_pack(sv[dl][k0 + 2], sv[dl][k0 + 3]);
            *(uint2*)(tile + row * 128 + (((u32)(k0 * 2)) ^ xv)) = make_uint2(p01, p23);
        }
        __syncthreads();
    }
}

// ============================================================
// score: 128x128 tile, K=128 in 2 chunks of 64, 3-pass bf16-split.
// smem 64KB -> 2 CTAs/SM. Register-only epilogue.
// ============================================================
#define SC_SMEM 65536
__global__ __launch_bounds__(256) void score_kernel() {
    extern __shared__ u8 sm[];
    const u32 sb = smem_u32(sm);
    const int t = threadIdx.x, lane = t & 31, wid = t >> 5;
    const int wm = wid & 1, wn = wid >> 1;
    const int b = blockIdx.z, mt = blockIdx.y, nt = blockIdx.x;

    const u8* a_hi = g_k1pack + ((size_t)(b * 16 + mt) * 2) * 32768;
    const u8* a_lo = a_hi + 32768;
    const u8* b_hi = g_k2pack + ((size_t)(b * 16 + nt) * 2) * 32768;
    const u8* b_lo = b_hi + 32768;

    float acc[4][4][4];
#pragma unroll
    for (int i = 0; i < 4; i++)
#pragma unroll
        for (int j = 0; j < 4; j++)
#pragma unroll
            for (int q = 0; q < 4; q++) acc[i][j][q] = 0.f;

    const int lr = lane & 15;
    for (int kc = 0; kc < 2; kc++) {
        __syncthreads();
        const u32 off0 = (u32)(kc * 16384);
#pragma unroll
        for (int j = 0; j < 4; j++) {
            const u32 o = (u32)((j * 256 + t) * 16);
            CP_ASYNC16(sb + o,         a_hi + off0 + o);
            CP_ASYNC16(sb + 16384 + o, a_lo + off0 + o);
            CP_ASYNC16(sb + 32768 + o, b_hi + off0 + o);
            CP_ASYNC16(sb + 49152 + o, b_lo + off0 + o);
        }
        CP_COMMIT(); CP_WAITG(0);
        __syncthreads();
#pragma unroll
        for (int ks = 0; ks < 4; ks++) {
            const u32 kb = (u32)((ks * 16 + (lane >> 4) * 8) * 2);
            u32 ah[4][4], al[4][4], bh[2][4], bl[2][4];
#pragma unroll
            for (int mf = 0; mf < 4; mf++) {
                const int r = wm * 64 + mf * 16 + lr;
                const u32 ro = (u32)(r * 128) + (kb ^ ((u32)((r & 7) * 16)));
                ldsm4(ah[mf], sb + ro);
                ldsm4(al[mf], sb + 16384 + ro);
            }
#pragma unroll
            for (int nb = 0; nb < 2; nb++) {
                const int r = wn * 32 + nb * 16 + lr;
                const u32 ro = (u32)(r * 128) + (kb ^ ((u32)((r & 7) * 16)));
                ldsm4(bh[nb], sb + 32768 + ro);
                ldsm4(bl[nb], sb + 49152 + ro);
            }
#pragma unroll
            for (int mf = 0; mf < 4; mf++)
#pragma unroll
                for (int n8 = 0; n8 < 4; n8++) {
                    const int nb = n8 >> 1, i = n8 & 1;
                    mma_bf16(acc[mf][n8], ah[mf], bh[nb][i], bh[nb][i + 2]);
                    mma_bf16(acc[mf][n8], al[mf], bh[nb][i], bh[nb][i + 2]);
                    mma_bf16(acc[mf][n8], ah[mf], bl[nb][i], bl[nb][i + 2]);
                }
        }
    }

    // register-only epilogue: direct S stores + shfl max partials
    const int g = lane >> 2, tig = lane & 3;
    float rowm[8], colm[8];
#pragma unroll
    for (int i = 0; i < 8; i++) { rowm[i] = NEG_INF; colm[i] = NEG_INF; }
    float* Sp = g_S + ((size_t)(b * N_ + mt * 128)) * N_ + nt * 128;
#pragma unroll
    for (int mf = 0; mf < 4; mf++) {
        const int r0 = wm * 64 + mf * 16 + g;
#pragma unroll
        for (int n8 = 0; n8 < 4; n8++) {
            const int c = wn * 32 + n8 * 8 + tig * 2;
            const float v0 = acc[mf][n8][0], v1 = acc[mf][n8][1];
            const float v2 = acc[mf][n8][2], v3 = acc[mf][n8][3];
            *(float2*)(Sp + (size_t)r0 * N_ + c)       = make_float2(v0, v1);
            *(float2*)(Sp + (size_t)(r0 + 8) * N_ + c) = make_float2(v2, v3);
            rowm[mf * 2 + 0] = fmaxf(rowm[mf * 2 + 0], fmaxf(v0, v1));
            rowm[mf * 2 + 1] = fmaxf(rowm[mf * 2 + 1], fmaxf(v2, v3));
            colm[n8 * 2 + 0] = fmaxf(colm[n8 * 2 + 0], fmaxf(v0, v2));
            colm[n8 * 2 + 1] = fmaxf(colm[n8 * 2 + 1], fmaxf(v1, v3));
        }
    }
#pragma unroll
    for (int i = 0; i < 8; i++) {
        rowm[i] = fmaxf(rowm[i], __shfl_xor_sync(0xffffffffu, rowm[i], 1));
        rowm[i] = fmaxf(rowm[i], __shfl_xor_sync(0xffffffffu, rowm[i], 2));
        colm[i] = fmaxf(colm[i], __shfl_xor_sync(0xffffffffu, colm[i], 4));
        colm[i] = fmaxf(colm[i], __shfl_xor_sync(0xffffffffu, colm[i], 8));
        colm[i] = fmaxf(colm[i], __shfl_xor_sync(0xffffffffu, colm[i], 16));
    }
    if (tig == 0) {
#pragma unroll
        for (int mf = 0; mf < 4; mf++)
#pragma unroll
            for (int rh = 0; rh < 2; rh++) {
                const int row = mt * 128 + wm * 64 + mf * 16 + rh * 8 + g;
                g_rmpart[((size_t)(b * N_ + row)) * 64 + nt * 4 + wn] = rowm[mf * 2 + rh];
            }
    }
    if (g == 0) {
#pragma unroll
        for (int n8 = 0; n8 < 4; n8++)
#pragma unroll
            for (int cp = 0; cp < 2; cp++) {
                const int col = nt * 128 + wn * 32 + n8 * 8 + tig * 2 + cp;
                g_cmpart[((size_t)(b * N_ + col)) * 32 + mt * 2 + wm] = colm[n8 * 2 + cp];
            }
    }
}

// ============================================================
__global__ void maxreduce_kernel() {
    const int which = blockIdx.y;
    const int i = blockIdx.x * 256 + threadIdx.x;
    if (which == 0) {
        const float* p = g_rmpart + (size_t)i * 64;
        float m = p[0];
#pragma unroll
        for (int j = 1; j < 64; j++) m = fmaxf(m, p[j]);
        g_rowmax[i] = m;
    } else {
        const float* p = g_cmpart + (size_t)i * 32;
        float m = p[0];
#pragma unroll
        for (int j = 1; j < 32; j++) m = fmaxf(m, p[j]);
        g_colmax[i] = m;
    }
}

// ============================================================
// o kernel (fused o1+o2, z = which): 64m x 256n tile, K=2048, fp16 mma
// ============================================================
#define O_SMEM 109568
__global__ __launch_bounds__(256) void o_kernel(float* __restrict__ o2_out,
                                                float* __restrict__ o1_out) {
    extern __shared__ u8 sm[];
    const u32 sb = smem_u32(sm);
    const int t = threadIdx.x, lane = t & 31, wid = t >> 5;
    const int wm = wid & 1, wn = wid >> 1;
    const int which = blockIdx.z;
    const int b = blockIdx.y, m0 = blockIdx.x * 64;
    float* red = (float*)(sm + 108544);

    const float* refm = which ? g_colmax : g_rowmax;
    const u8*    vp   = which ? g_v1pack : g_v2pack;
    float* outp = which ? o1_out : o2_out;
    const float* Sb = g_S + (size_t)b * N_ * N_;

    const u32 VB = sb, SST = sb + 65536, AF = sb + 100352;

    const int pm = t & 63, pq = (t >> 6) * 16;
    const float rm = refm[b * N_ + m0 + pm];
    const u32 axv = (u32)((pm & 7) * 16);

    float acc[2][8][4];
#pragma unroll
    for (int i = 0; i < 2; i++)
#pragma unroll
        for (int j = 0; j < 8; j++)
#pragma unroll
            for (int q = 0; q < 4; q++) acc[i][j][q] = 0.f;

    auto issue = [&](int cc) {
        const int p = cc & 1;
        {   // V: 32KB straight copy
            const u8* src = vp + ((size_t)b * 32 + cc) * 32768 + t * 128;
            const u32 dst = VB + (u32)(p * 32768 + t * 128);
#pragma unroll
            for (int i = 0; i < 8; i++) CP_ASYNC16(dst + i * 16, src + i * 16);
        }
        {   // S: 64 rows x 256B, pitch 272
            const int r = t >> 2, q = (t & 3) * 64;
            const float* src = which
                ? (Sb + (size_t)(cc * 64 + r) * N_ + m0)
                : (Sb + (size_t)(m0 + r) * N_ + cc * 64);
            const u32 dst = SST + (u32)(p * 17408 + r * 272 + q);
#pragma unroll
            for (int i = 0; i < 4; i++) CP_ASYNC16(dst + i * 16, (const u8*)src + q + i * 16);
        }
        CP_COMMIT();
    };

    issue(0);
    float rsum = 0.f;
    const int lr = lane & 15;

    for (int c = 0; c < 32; c++) {
        const int p = c & 1;
        if (c + 1 < 32) { issue(c + 1); CP_WAITG(1); }
        else            { CP_WAITG(0); }
        __syncthreads();
        // pack A: exp + fp16
        {
            const float* st = (const float*)(sm + 65536 + p * 17408);
            float e[16];
            if (which == 0) {
                const float* rowp = st + pm * 68 + pq;
#pragma unroll
                for (int j = 0; j < 16; j += 4) {
                    float4 f = *(const float4*)(rowp + j);
                    e[j] = __expf(f.x - rm); e[j + 1] = __expf(f.y - rm);
                    e[j + 2] = __expf(f.z - rm); e[j + 3] = __expf(f.w - rm);
                }
            } else {
#pragma unroll
                for (int j = 0; j < 16; j++)
                    e[j] = __expf(st[(pq + j) * 68 + pm] - rm);
            }
#pragma unroll
            for (int j = 0; j < 16; j++) rsum += e[j];
#pragma unroll
            for (int j = 0; j < 4; j++) {
                u32 p01 = f16x2_pack(e[4 * j + 0], e[4 * j + 1]);
                u32 p23 = f16x2_pack(e[4 * j + 2], e[4 * j + 3]);
                const u32 off = (u32)(pm * 128) + (((u32)((pq + 4 * j) * 2)) ^ axv);
                *(uint2*)(sm + 100352 + off) = make_uint2(p01, p23);
            }
        }
        __syncthreads();
        // mma: A 64x64 f16, B (V) 256x64 f16
#pragma unroll
        for (int ks = 0; ks < 4; ks++) {
            const u32 kb = (u32)((ks * 16 + (lane >> 4) * 8) * 2);
            u32 a[2][4], bb[4][4];
#pragma unroll
            for (int mf = 0; mf < 2; mf++) {
                const int r = wm * 32 + mf * 16 + lr;
                ldsm4(a[mf], AF + (u32)(r * 128) + (kb ^ ((u32)((r & 7) * 16))));
            }
#pragma unroll
            for (int nb = 0; nb < 4; nb++) {
                const int r = wn * 64 + nb * 16 + lr;
                ldsm4(bb[nb], VB + (u32)(p * 32768 + r * 128) + (kb ^ ((u32)((r & 7) * 16))));
            }
#pragma unroll
            for (int mf = 0; mf < 2; mf++)
#pragma unroll
                for (int n8 = 0; n8 < 8; n8++) {
                    const int nb = n8 >> 1, i = n8 & 1;
                    mma_f16(acc[mf][n8], a[mf], bb[nb][i], bb[nb][i + 2]);
                }
        }
        __syncthreads();   // protect buffer p before issue(c+2)
    }
    red[t] = rsum;
    __syncthreads();
    const int g = lane >> 2, tig = lane & 3;
#pragma unroll
    for (int mf = 0; mf < 2; mf++) {
        const int r0 = wm * 32 + mf * 16 + g;
        const int r1 = r0 + 8;
        const float inv0 = 1.f / (red[r0] + red[r0 + 64] + red[r0 + 128] + red[r0 + 192]);
        const float inv1 = 1.f / (red[r1] + red[r1 + 64] + red[r1 + 128] + red[r1 + 192]);
        float* po0 = outp + ((size_t)(b * N_ + m0 + r0)) * VD;
        float* po1 = outp + ((size_t)(b * N_ + m0 + r1)) * VD;
#pragma unroll
        for (int n8 = 0; n8 < 8; n8++) {
            const int cc = wn * 64 + n8 * 8 + tig * 2;
            *(float2*)(po0 + cc) = make_float2(acc[mf][n8][0] * inv0, acc[mf][n8][1] * inv0);
            *(float2*)(po1 + cc) = make_float2(acc[mf][n8][2] * inv1, acc[mf][n8][3] * inv1);
        }
    }
}

// ============================================================
extern "C" void kernel_launch(void* const* d_in, const int* in_sizes, int n_in,
                              void* d_out, int out_size) {
    (void)in_sizes; (void)n_in; (void)out_size;
    const float* k1 = (const float*)d_in[0];
    const float* k2 = (const float*)d_in[1];
    const float* v1 = (const float*)d_in[2];
    const float* v2 = (const float*)d_in[3];
    const float* W1 = (const float*)d_in[4];
    const float* b1 = (const float*)d_in[5];
    const float* W2 = (const float*)d_in[6];
    const float* b2 = (const float*)d_in[7];
    float* out = (float*)d_out;
    float* o2_out = out;
    float* o1_out = out + (size_t)B_ * N_ * VD;

    cudaFuncSetAttribute(proj_kernel, cudaFuncAttributeMaxDynamicSharedMemorySize, P_SMEM);
    cudaFuncSetAttribute(score_kernel, cudaFuncAttributeMaxDynamicSharedMemorySize, SC_SMEM);
    cudaFuncSetAttribute(o_kernel, cudaFuncAttributeMaxDynamicSharedMemorySize, O_SMEM);

    // FIX R8: proj must cover all B_*N_ = 16384 rows -> 128 CTAs in x (was 64)
    proj_kernel<<<dim3(128, 2), 256, P_SMEM>>>(k1, W1, b1, k2, W2, b2);
    vpack_kernel<<<dim3(32, B_, 2), 256>>>(v1, v2);

    score_kernel<<<dim3(16, 16, B_), 256, SC_SMEM>>>();

    maxreduce_kernel<<<dim3((B_ * N_) / 256, 2), 256>>>();

    o_kernel<<<dim3(32, B_, 2), 256, O_SMEM>>>(o2_out, o1_out);
}

// round 10
// speedup vs baseline: 3.1152x; 1.0594x over previous
#include <cuda_runtime.h>
#include <cuda_fp16.h>
#include <cstdint>
#include <cstddef>

#define B_  8
#define N_  2048
#define KD  256
#define VD  256
#define AD  128
#define NEG_INF (-3.402823466e38f)

typedef unsigned char u8;
typedef unsigned int  u32;

// ------------------- device scratch -------------------
__device__ __align__(16) u8 g_k1pack[(size_t)B_ * 16 * 2 * 32768];   // 8 MB
__device__ __align__(16) u8 g_k2pack[(size_t)B_ * 16 * 2 * 32768];   // 8 MB
__device__ __align__(16) u8 g_v1pack[(size_t)B_ * 32 * 32768];       // 8 MB
__device__ __align__(16) u8 g_v2pack[(size_t)B_ * 32 * 32768];       // 8 MB
__device__ float g_S[(size_t)B_ * N_ * N_];                          // 128 MB
// exp-packed A operands: per (b, tile16, kc32): [128 rows][64 k] fp16 swizzled (16KB)
__device__ __align__(16) u8 g_A2[(size_t)B_ * 16 * 32 * 16384];      // 64 MB
__device__ __align__(16) u8 g_A1[(size_t)B_ * 16 * 32 * 16384];      // 64 MB
__device__ float g_rmpart[(size_t)B_ * N_ * 64];
__device__ float g_cmpart[(size_t)B_ * N_ * 32];
__device__ float g_rspart[(size_t)B_ * N_ * 32];
__device__ float g_cspart[(size_t)B_ * N_ * 32];
__device__ float g_rowmax[B_ * N_];
__device__ float g_colmax[B_ * N_];
__device__ float g_rsinv[B_ * N_];
__device__ float g_csinv[B_ * N_];

// ------------------- helpers -------------------
__device__ __forceinline__ u32 smem_u32(const void* p) {
    u32 a;
    asm("{ .reg .u64 t; cvta.to.shared.u64 t, %1; cvt.u32.u64 %0, t; }" : "=r"(a) : "l"(p));
    return a;
}
__device__ __forceinline__ u32 f16x2_pack(float a, float b) {
    u32 r;
    asm("cvt.rn.f16x2.f32 %0, %1, %2;" : "=r"(r) : "f"(b), "f"(a));
    return r;
}
__device__ __forceinline__ void split2(float f0, float f1, u32& hi, u32& lo) {
    u32 h;
    asm("cvt.rn.bf16x2.f32 %0, %1, %2;" : "=r"(h) : "f"(f1), "f"(f0));
    float h0 = __uint_as_float(h << 16);
    float h1 = __uint_as_float(h & 0xFFFF0000u);
    u32 l;
    asm("cvt.rn.bf16x2.f32 %0, %1, %2;" : "=r"(l) : "f"(f1 - h1), "f"(f0 - h0));
    hi = h; lo = l;
}
__device__ __forceinline__ void mma_bf16(float* c, const u32* a, u32 b0, u32 b1) {
    asm volatile(
        "mma.sync.aligned.m16n8k16.row.col.f32.bf16.bf16.f32 "
        "{%0,%1,%2,%3}, {%4,%5,%6,%7}, {%8,%9}, {%0,%1,%2,%3};"
        : "+f"(c[0]), "+f"(c[1]), "+f"(c[2]), "+f"(c[3])
        : "r"(a[0]), "r"(a[1]), "r"(a[2]), "r"(a[3]), "r"(b0), "r"(b1));
}
__device__ __forceinline__ void mma_f16(float* c, const u32* a, u32 b0, u32 b1) {
    asm volatile(
        "mma.sync.aligned.m16n8k16.row.col.f32.f16.f16.f32 "
        "{%0,%1,%2,%3}, {%4,%5,%6,%7}, {%8,%9}, {%0,%1,%2,%3};"
        : "+f"(c[0]), "+f"(c[1]), "+f"(c[2]), "+f"(c[3])
        : "r"(a[0]), "r"(a[1]), "r"(a[2]), "r"(a[3]), "r"(b0), "r"(b1));
}
__device__ __forceinline__ void ldsm4(u32* r, u32 addr) {
    asm volatile("ldmatrix.sync.aligned.m8n8.x4.shared.b16 {%0,%1,%2,%3}, [%4];"
                 : "=r"(r[0]), "=r"(r[1]), "=r"(r[2]), "=r"(r[3]) : "r"(addr));
}
#define CP_ASYNC16(dst, src)                                                \
    asm volatile("cp.async.cg.shared.global [%0], [%1], 16;"                \
                 :: "r"(dst), "l"(__cvta_generic_to_global(src)))
#define CP_COMMIT()  asm volatile("cp.async.commit_group;")
#define CP_WAITG(n)  asm volatile("cp.async.wait_group %0;" :: "n"(n))

// ============================================================
// proj (merged): C = A[M,256] @ W + bias -> split bf16 pack  (unchanged R9)
// ============================================================
#define P_SMEM 99840
__global__ __launch_bounds__(256) void proj_kernel(const float* __restrict__ k1,
                                                   const float* __restrict__ W1,
                                                   const float* __restrict__ b1v,
                                                   const float* __restrict__ k2,
                                                   const float* __restrict__ W2,
                                                   const float* __restrict__ b2v) {
    extern __shared__ u8 sm[];
    const u32 sb = smem_u32(sm);
    float* Wst = (float*)(sm + 65536);
    float* bc  = (float*)(sm + 99328);
    const int which = blockIdx.y;
    const float* A = which ? k2 : k1;
    const float* W = which ? W2 : W1;
    const float* bias = which ? b2v : b1v;
    const int t = threadIdx.x, lane = t & 31, wid = t >> 5;
    const int wm = wid & 1, wn = wid >> 1;
    const int m0 = blockIdx.x * 128;
    if (t < 128) bc[t] = bias[t];

    float acc[4][4][4];
#pragma unroll
    for (int i = 0; i < 4; i++)
#pragma unroll
        for (int j = 0; j < 4; j++)
#pragma unroll
            for (int q = 0; q < 4; q++) acc[i][j][q] = 0.f;

    const int lr = lane & 15;
    for (int kc = 0; kc < 4; kc++) {
        __syncthreads();
        {
            const int m = t >> 1, kh = (t & 1) * 32;
            const float* Ar = A + (size_t)(m0 + m) * KD + kc * 64 + kh;
            const u32 xv = (u32)((m & 7) * 16);
#pragma unroll
            for (int j = 0; j < 8; j++) {
                float4 f = *(const float4*)(Ar + 4 * j);
                u32 h01, l01, h23, l23;
                split2(f.x, f.y, h01, l01); split2(f.z, f.w, h23, l23);
                const u32 off = (u32)(m * 128) + (((u32)((kh + 4 * j) * 2)) ^ xv);
                *(uint2*)(sm + off)         = make_uint2(h01, h23);
                *(uint2*)(sm + 16384 + off) = make_uint2(l01, l23);
            }
        }
        {
            const int k = t >> 2, ns = (t & 3) * 32;
            const float* Wr = W + (size_t)(kc * 64 + k) * AD + ns;
#pragma unroll
            for (int j = 0; j < 8; j++)
                *(float4*)&Wst[k * 132 + ns + 4 * j] = *(const float4*)(Wr + 4 * j);
        }
        __syncthreads();
        {
            const int n = t >> 1, kh = (t & 1) * 32;
            const u32 xv = (u32)((n & 7) * 16);
#pragma unroll
            for (int jq = 0; jq < 8; jq++) {
                float w0 = Wst[(kh + 4 * jq + 0) * 132 + n];
                float w1 = Wst[(kh + 4 * jq + 1) * 132 + n];
                float w2 = Wst[(kh + 4 * jq + 2) * 132 + n];
                float w3 = Wst[(kh + 4 * jq + 3) * 132 + n];
                u32 h01, l01, h23, l23;
                split2(w0, w1, h01, l01); split2(w2, w3, h23, l23);
                const u32 off = (u32)(n * 128) + (((u32)((kh + 4 * jq) * 2)) ^ xv);
                *(uint2*)(sm + 32768 + off) = make_uint2(h01, h23);
                *(uint2*)(sm + 49152 + off) = make_uint2(l01, l23);
            }
        }
        __syncthreads();
#pragma unroll
        for (int ks = 0; ks < 4; ks++) {
            const u32 kb = (u32)((ks * 16 + (lane >> 4) * 8) * 2);
            u32 ah[4][4], al[4][4], bh[2][4], bl[2][4];
#pragma unroll
            for (int mf = 0; mf < 4; mf++) {
                const int r = wm * 64 + mf * 16 + lr;
                const u32 ro = (u32)(r * 128) + (kb ^ ((u32)((r & 7) * 16)));
                ldsm4(ah[mf], sb + ro);
                ldsm4(al[mf], sb + 16384 + ro);
            }
#pragma unroll
            for (int nb = 0; nb < 2; nb++) {
                const int r = wn * 32 + nb * 16 + lr;
                const u32 ro = (u32)(r * 128) + (kb ^ ((u32)((r & 7) * 16)));
                ldsm4(bh[nb], sb + 32768 + ro);
                ldsm4(bl[nb], sb + 49152 + ro);
            }
#pragma unroll
            for (int mf = 0; mf < 4; mf++)
#pragma unroll
                for (int n8 = 0; n8 < 4; n8++) {
                    const int nb = n8 >> 1, i = n8 & 1;
                    mma_bf16(acc[mf][n8], ah[mf], bh[nb][i], bh[nb][i + 2]);
                    mma_bf16(acc[mf][n8], al[mf], bh[nb][i], bh[nb][i + 2]);
                    mma_bf16(acc[mf][n8], ah[mf], bl[nb][i], bl[nb][i + 2]);
                }
        }
    }
    __syncthreads();
    float* smT = (float*)sm;
    const int g = lane >> 2, tig = lane & 3;
#pragma unroll
    for (int mf = 0; mf < 4; mf++)
#pragma unroll
        for (int n8 = 0; n8 < 4; n8++) {
            const int r = wm * 64 + mf * 16 + g;
            const int c = wn * 32 + n8 * 8 + tig * 2;
            const float b0 = bc[c], b1 = bc[c + 1];
            *(float2*)&smT[r * 132 + c]       = make_float2(acc[mf][n8][0] + b0, acc[mf][n8][1] + b1);
            *(float2*)&smT[(r + 8) * 132 + c] = make_float2(acc[mf][n8][2] + b0, acc[mf][n8][3] + b1);
        }
    __syncthreads();
    {
        const int b_ = m0 / N_, mt = (m0 % N_) / 128;
        u8* hibase = (which ? g_k2pack : g_k1pack) + ((size_t)(b_ * 16 + mt) * 2) * 32768;
        u8* lobase = hibase + 32768;
        const int row = t >> 1, ch = t & 1;
        const u32 xv = (u32)((row & 7) * 16);
#pragma unroll
        for (int j = 0; j < 16; j++) {
            float f0 = smT[row * 132 + ch * 64 + 4 * j + 0];
            float f1 = smT[row * 132 + ch * 64 + 4 * j + 1];
            float f2 = smT[row * 132 + ch * 64 + 4 * j + 2];
            float f3 = smT[row * 132 + ch * 64 + 4 * j + 3];
            u32 h01, l01, h23, l23;
            split2(f0, f1, h01, l01); split2(f2, f3, h23, l23);
            const u32 off = (u32)(ch * 16384 + row * 128) + (((u32)(8 * j)) ^ xv);
            *(uint2*)(hibase + off) = make_uint2(h01, h23);
            *(uint2*)(lobase + off) = make_uint2(l01, l23);
        }
    }
}

// ============================================================
// vpack (unchanged R9)
// ============================================================
__global__ __launch_bounds__(256) void vpack_kernel(const float* __restrict__ v1,
                                                    const float* __restrict__ v2) {
    __shared__ float sv[64][68];
    const int which = blockIdx.z;
    const float* v = which ? v2 : v1;
    u8* dst = which ? g_v2pack : g_v1pack;
    const int b = blockIdx.y, kc = blockIdx.x;
    const int t = threadIdx.x;
    u8* tile = dst + ((size_t)b * 32 + kc) * 32768;
    for (int dc = 0; dc < 4; dc++) {
#pragma unroll
        for (int i = 0; i < 4; i++) {
            const int q = t + i * 256;
            const int kr = q >> 4, dl = (q & 15) * 4;
            float4 f = *(const float4*)(v + ((size_t)b * N_ + kc * 64 + kr) * VD + dc * 64 + dl);
            sv[dl + 0][kr] = f.x; sv[dl + 1][kr] = f.y;
            sv[dl + 2][kr] = f.z; sv[dl + 3][kr] = f.w;
        }
        __syncthreads();
        const int dl = t >> 2, q = t & 3;
        const int row = dc * 64 + dl;
        const u32 xv = (u32)((row & 7) * 16);
#pragma unroll
        for (int j = 0; j < 4; j++) {
            const int k0 = q * 16 + j * 4;
            u32 p01 = f16x2_pack(sv[dl][k0 + 0], sv[dl][k0 + 1]);
            u32 p23 = f16x2_pack(sv[dl][k0 + 2], sv[dl][k0 + 3]);
            *(uint2*)(tile + row * 128 + (((u32)(k0 * 2)) ^ xv)) = make_uint2(p01, p23);
        }
        __syncthreads();
    }
}

// ============================================================
// score (unchanged R9): 128x128, register epilogue, S + max partials
// ============================================================
#define SC_SMEM 65536
__global__ __launch_bounds__(256) void score_kernel() {
    extern __shared__ u8 sm[];
    const u32 sb = smem_u32(sm);
    const int t = threadIdx.x, lane = t & 31, wid = t >> 5;
    const int wm = wid & 1, wn = wid >> 1;
    const int b = blockIdx.z, mt = blockIdx.y, nt = blockIdx.x;

    const u8* a_hi = g_k1pack + ((size_t)(b * 16 + mt) * 2) * 32768;
    const u8* a_lo = a_hi + 32768;
    const u8* b_hi = g_k2pack + ((size_t)(b * 16 + nt) * 2) * 32768;
    const u8* b_lo = b_hi + 32768;

    float acc[4][4][4];
#pragma unroll
    for (int i = 0; i < 4; i++)
#pragma unroll
        for (int j = 0; j < 4; j++)
#pragma unroll
            for (int q = 0; q < 4; q++) acc[i][j][q] = 0.f;

    const int lr = lane & 15;
    for (int kc = 0; kc < 2; kc++) {
        __syncthreads();
        const u32 off0 = (u32)(kc * 16384);
#pragma unroll
        for (int j = 0; j < 4; j++) {
            const u32 o = (u32)((j * 256 + t) * 16);
            CP_ASYNC16(sb + o,         a_hi + off0 + o);
            CP_ASYNC16(sb + 16384 + o, a_lo + off0 + o);
            CP_ASYNC16(sb + 32768 + o, b_hi + off0 + o);
            CP_ASYNC16(sb + 49152 + o, b_lo + off0 + o);
        }
        CP_COMMIT(); CP_WAITG(0);
        __syncthreads();
#pragma unroll
        for (int ks = 0; ks < 4; ks++) {
            const u32 kb = (u32)((ks * 16 + (lane >> 4) * 8) * 2);
            u32 ah[4][4], al[4][4], bh[2][4], bl[2][4];
#pragma unroll
            for (int mf = 0; mf < 4; mf++) {
                const int r = wm * 64 + mf * 16 + lr;
                const u32 ro = (u32)(r * 128) + (kb ^ ((u32)((r & 7) * 16)));
                ldsm4(ah[mf], sb + ro);
                ldsm4(al[mf], sb + 16384 + ro);
            }
#pragma unroll
            for (int nb = 0; nb < 2; nb++) {
                const int r = wn * 32 + nb * 16 + lr;
                const u32 ro = (u32)(r * 128) + (kb ^ ((u32)((r & 7) * 16)));
                ldsm4(bh[nb], sb + 32768 + ro);
                ldsm4(bl[nb], sb + 49152 + ro);
            }
#pragma unroll
            for (int mf = 0; mf < 4; mf++)
#pragma unroll
                for (int n8 = 0; n8 < 4; n8++) {
                    const int nb = n8 >> 1, i = n8 & 1;
                    mma_bf16(acc[mf][n8], ah[mf], bh[nb][i], bh[nb][i + 2]);
                    mma_bf16(acc[mf][n8], al[mf], bh[nb][i], bh[nb][i + 2]);
                    mma_bf16(acc[mf][n8], ah[mf], bl[nb][i], bl[nb][i + 2]);
                }
        }
    }

    const int g = lane >> 2, tig = lane & 3;
    float rowm[8], colm[8];
#pragma unroll
    for (int i = 0; i < 8; i++) { rowm[i] = NEG_INF; colm[i] = NEG_INF; }
    float* Sp = g_S + ((size_t)(b * N_ + mt * 128)) * N_ + nt * 128;
#pragma unroll
    for (int mf = 0; mf < 4; mf++) {
        const int r0 = wm * 64 + mf * 16 + g;
#pragma unroll
        for (int n8 = 0; n8 < 4; n8++) {
            const int c = wn * 32 + n8 * 8 + tig * 2;
            const float v0 = acc[mf][n8][0], v1 = acc[mf][n8][1];
            const float v2 = acc[mf][n8][2], v3 = acc[mf][n8][3];
            *(float2*)(Sp + (size_t)r0 * N_ + c)       = make_float2(v0, v1);
            *(float2*)(Sp + (size_t)(r0 + 8) * N_ + c) = make_float2(v2, v3);
            rowm[mf * 2 + 0] = fmaxf(rowm[mf * 2 + 0], fmaxf(v0, v1));
            rowm[mf * 2 + 1] = fmaxf(rowm[mf * 2 + 1], fmaxf(v2, v3));
            colm[n8 * 2 + 0] = fmaxf(colm[n8 * 2 + 0], fmaxf(v0, v2));
            colm[n8 * 2 + 1] = fmaxf(colm[n8 * 2 + 1], fmaxf(v1, v3));
        }
    }
#pragma unroll
    for (int i = 0; i < 8; i++) {
        rowm[i] = fmaxf(rowm[i], __shfl_xor_sync(0xffffffffu, rowm[i], 1));
        rowm[i] = fmaxf(rowm[i], __shfl_xor_sync(0xffffffffu, rowm[i], 2));
        colm[i] = fmaxf(colm[i], __shfl_xor_sync(0xffffffffu, colm[i], 4));
        colm[i] = fmaxf(colm[i], __shfl_xor_sync(0xffffffffu, colm[i], 8));
        colm[i] = fmaxf(colm[i], __shfl_xor_sync(0xffffffffu, colm[i], 16));
    }
    if (tig == 0) {
#pragma unroll
        for (int mf = 0; mf < 4; mf++)
#pragma unroll
            for (int rh = 0; rh < 2; rh++) {
                const int row = mt * 128 + wm * 64 + mf * 16 + rh * 8 + g;
                g_rmpart[((size_t)(b * N_ + row)) * 64 + nt * 4 + wn] = rowm[mf * 2 + rh];
            }
    }
    if (g == 0) {
#pragma unroll
        for (int n8 = 0; n8 < 4; n8++)
#pragma unroll
            for (int cp = 0; cp < 2; cp++) {
                const int col = nt * 128 + wn * 32 + n8 * 8 + tig * 2 + cp;
                g_cmpart[((size_t)(b * N_ + col)) * 32 + mt * 2 + wm] = colm[n8 * 2 + cp];
            }
    }
}

// ============================================================
__global__ void maxreduce_kernel() {
    const int which = blockIdx.y;
    const int i = blockIdx.x * 256 + threadIdx.x;
    if (which == 0) {
        const float* p = g_rmpart + (size_t)i * 64;
        float m = p[0];
#pragma unroll
        for (int j = 1; j < 64; j++) m = fmaxf(m, p[j]);
        g_rowmax[i] = m;
    } else {
        const float* p = g_cmpart + (size_t)i * 32;
        float m = p[0];
#pragma unroll
        for (int j = 1; j < 32; j++) m = fmaxf(m, p[j]);
        g_colmax[i] = m;
    }
}

// ============================================================
// exppack: per 128x128 S tile -> A2 (exp(s-rm), rows=m) and A1 (exp(s-cm),
// rows=n, transposed) fp16 swizzled 16KB tiles + row/col sum partials.
// smem: smS fp32 [128][132] @0 (67584) | smPack @67584: 2 tiles pitch 144, HOFF 18448
// ============================================================
#define HOFF 18448
#define E_SMEM (67584 + 36880)
__global__ __launch_bounds__(256, 2) void exppack_kernel() {
    extern __shared__ u8 sm[];
    float* smS = (float*)sm;                  // [128][132]
    u8* smP = sm + 67584;
    const int t = threadIdx.x;
    const int b = blockIdx.z, mt = blockIdx.y, nt = blockIdx.x;

    // Phase A: coalesced S rows -> raw s to smS, exp(s-rm) -> A2 staging
    {
        const int row = t >> 1, h = t & 1;
        const float* Sp = g_S + ((size_t)(b * N_ + mt * 128 + row)) * N_ + nt * 128 + h * 64;
        const float rm = g_rowmax[b * N_ + mt * 128 + row];
        float rs = 0.f;
        u8* stage = smP + h * HOFF + row * 144;
        const u32 xv = (u32)((row & 7) * 16);
        float* smrow = &smS[row * 132 + h * 64];
#pragma unroll
        for (int jq = 0; jq < 16; jq++) {
            float4 f = *(const float4*)(Sp + jq * 4);
            *(float4*)(smrow + jq * 4) = f;
            float e0 = __expf(f.x - rm), e1 = __expf(f.y - rm);
            float e2 = __expf(f.z - rm), e3 = __expf(f.w - rm);
            rs += (e0 + e1) + (e2 + e3);
            *(uint2*)(stage + (((u32)(8 * jq)) ^ xv)) =
                make_uint2(f16x2_pack(e0, e1), f16x2_pack(e2, e3));
        }
        g_rspart[((size_t)(b * N_ + mt * 128 + row)) * 32 + nt * 2 + h] = rs;
    }
    __syncthreads();
    // copy out A2 (coalesced: 8 lanes cover one 128B row)
    {
        const int ch = t & 7;
#pragma unroll
        for (int p = 0; p < 8; p++) {
            const int rowg = (t >> 3) + p * 32;       // 0..255
            const int h = rowg >> 7, r = rowg & 127;
            const u8* src = smP + h * HOFF + (u32)(r * 144 + ch * 16);
            u8* dst = g_A2 + (((size_t)(b * 16 + mt) * 32) + nt * 2 + h) * 16384 + r * 128 + ch * 16;
            *(uint4*)dst = *(const uint4*)src;
        }
    }
    __syncthreads();
    // Phase C: transposed exp(s-cm) -> A1 staging
    {
        const int col = t & 127, mseg = t >> 7;
        const float cm = g_colmax[b * N_ + nt * 128 + col];
        float cs = 0.f;
        u8* stage = smP + mseg * HOFF + col * 144;
        const u32 xv = (u32)((col & 7) * 16);
#pragma unroll
        for (int jq = 0; jq < 16; jq++) {
            const int m4 = mseg * 64 + jq * 4;
            float s0 = smS[(m4 + 0) * 132 + col];
            float s1 = smS[(m4 + 1) * 132 + col];
            float s2 = smS[(m4 + 2) * 132 + col];
            float s3 = smS[(m4 + 3) * 132 + col];
            float e0 = __expf(s0 - cm), e1 = __expf(s1 - cm);
            float e2 = __expf(s2 - cm), e3 = __expf(s3 - cm);
            cs += (e0 + e1) + (e2 + e3);
            *(uint2*)(stage + (((u32)(8 * jq)) ^ xv)) =
                make_uint2(f16x2_pack(e0, e1), f16x2_pack(e2, e3));
        }
        g_cspart[((size_t)(b * N_ + nt * 128 + col)) * 32 + mt * 2 + mseg] = cs;
    }
    __syncthreads();
    // copy out A1
    {
        const int ch = t & 7;
#pragma unroll
        for (int p = 0; p < 8; p++) {
            const int rowg = (t >> 3) + p * 32;
            const int ms = rowg >> 7, r = rowg & 127;
            const u8* src = smP + ms * HOFF + (u32)(r * 144 + ch * 16);
            u8* dst = g_A1 + (((size_t)(b * 16 + nt) * 32) + mt * 2 + ms) * 16384 + r * 128 + ch * 16;
            *(uint4*)dst = *(const uint4*)src;
        }
    }
}

// ============================================================
__global__ void sumreduce_kernel() {
    const int which = blockIdx.y;
    const int i = blockIdx.x * 256 + threadIdx.x;
    const float* p = (which ? g_cspart : g_rspart) + (size_t)i * 32;
    float s = 0.f;
#pragma unroll
    for (int j = 0; j < 32; j++) s += p[j];
    (which ? g_csinv : g_rsinv)[i] = 1.f / s;
}

// ============================================================
// o (pure GEMM, fused z=which): 128m x 128n, K=2048, fp16 mma, 3-stage pipeline
// smem: A 3x16K @0 | V 3x16K @49152  (96KB, 2 CTAs/SM)
// ============================================================
#define O_SMEM 98304
__global__ __launch_bounds__(256, 2) void o_kernel(float* __restrict__ o2_out,
                                                   float* __restrict__ o1_out) {
    extern __shared__ u8 sm[];
    const u32 sb = smem_u32(sm);
    const int t = threadIdx.x, lane = t & 31, wid = t >> 5;
    const int wm = wid & 1, wn = wid >> 1;
    const int which = blockIdx.z, b = blockIdx.y;
    const int mt = blockIdx.x >> 1, ntv = blockIdx.x & 1;

    const u8* Abase = (which ? g_A1 : g_A2) + ((size_t)(b * 16 + mt) * 32) * 16384;
    const u8* Vbase = (which ? g_v1pack : g_v2pack) + ((size_t)b * 32) * 32768 + (size_t)ntv * 16384;
    const float* inv = (which ? g_csinv : g_rsinv) + b * N_ + mt * 128;
    float* outp = which ? o1_out : o2_out;

    float acc[4][4][4];
#pragma unroll
    for (int i = 0; i < 4; i++)
#pragma unroll
        for (int j = 0; j < 4; j++)
#pragma unroll
            for (int q = 0; q < 4; q++) acc[i][j][q] = 0.f;

    auto issue = [&](int cc) {
        const int s3 = cc % 3;
        const u8* asrc = Abase + (size_t)cc * 16384 + t * 64;
        const u8* vsrc = Vbase + (size_t)cc * 32768 + t * 64;
        const u32 ad = sb + (u32)(s3 * 16384 + t * 64);
        const u32 vd = sb + 49152 + (u32)(s3 * 16384 + t * 64);
#pragma unroll
        for (int i = 0; i < 4; i++) CP_ASYNC16(ad + i * 16, asrc + i * 16);
#pragma unroll
        for (int i = 0; i < 4; i++) CP_ASYNC16(vd + i * 16, vsrc + i * 16);
        CP_COMMIT();
    };

    issue(0); issue(1);
    const int lr = lane & 15;

    for (int c = 0; c < 32; c++) {
        if (c < 31) { CP_WAITG(1); } else { CP_WAITG(0); }
        __syncthreads();               // all warps done with mma(c-1); chunk c visible
        if (c + 2 < 32) issue(c + 2);  // buf (c+2)%3 == (c-1)%3, freed by the sync
        const u32 AB = sb + (u32)((c % 3) * 16384);
        const u32 VB = sb + 49152 + (u32)((c % 3) * 16384);
#pragma unroll
        for (int ks = 0; ks < 4; ks++) {
            const u32 kb = (u32)((ks * 16 + (lane >> 4) * 8) * 2);
            u32 a[4][4], bv[2][4];
#pragma unroll
            for (int mf = 0; mf < 4; mf++) {
                const int r = wm * 64 + mf * 16 + lr;
                ldsm4(a[mf], AB + (u32)(r * 128) + (kb ^ ((u32)((r & 7) * 16))));
            }
#pragma unroll
            for (int nb = 0; nb < 2; nb++) {
                const int r = wn * 32 + nb * 16 + lr;
                ldsm4(bv[nb], VB + (u32)(r * 128) + (kb ^ ((u32)((r & 7) * 16))));
            }
#pragma unroll
            for (int mf = 0; mf < 4; mf++)
#pragma unroll
                for (int n8 = 0; n8 < 4; n8++) {
                    const int nb = n8 >> 1, i = n8 & 1;
                    mma_f16(acc[mf][n8], a[mf], bv[nb][i], bv[nb][i + 2]);
                }
        }
    }

    // epilogue: scale by 1/sum, store
    const int g = lane >> 2, tig = lane & 3;
#pragma unroll
    for (int mf = 0; mf < 4; mf++) {
        const int r0 = wm * 64 + mf * 16 + g;
        const int r1 = r0 + 8;
        const float inv0 = inv[r0], inv1 = inv[r1];
        float* po0 = outp + ((size_t)(b * N_ + mt * 128 + r0)) * VD + ntv * 128;
        float* po1 = outp + ((size_t)(b * N_ + mt * 128 + r1)) * VD + ntv * 128;
#pragma unroll
        for (int n8 = 0; n8 < 4; n8++) {
            const int cc = wn * 32 + n8 * 8 + tig * 2;
            *(float2*)(po0 + cc) = make_float2(acc[mf][n8][0] * inv0, acc[mf][n8][1] * inv0);
            *(float2*)(po1 + cc) = make_float2(acc[mf][n8][2] * inv1, acc[mf][n8][3] * inv1);
        }
    }
}

// ============================================================
extern "C" void kernel_launch(void* const* d_in, const int* in_sizes, int n_in,
                              void* d_out, int out_size) {
    (void)in_sizes; (void)n_in; (void)out_size;
    const float* k1 = (const float*)d_in[0];
    const float* k2 = (const float*)d_in[1];
    const float* v1 = (const float*)d_in[2];
    const float* v2 = (const float*)d_in[3];
    const float* W1 = (const float*)d_in[4];
    const float* b1 = (const float*)d_in[5];
    const float* W2 = (const float*)d_in[6];
    const float* b2 = (const float*)d_in[7];
    float* out = (float*)d_out;
    float* o2_out = out;
    float* o1_out = out + (size_t)B_ * N_ * VD;

    cudaFuncSetAttribute(proj_kernel, cudaFuncAttributeMaxDynamicSharedMemorySize, P_SMEM);
    cudaFuncSetAttribute(score_kernel, cudaFuncAttributeMaxDynamicSharedMemorySize, SC_SMEM);
    cudaFuncSetAttribute(exppack_kernel, cudaFuncAttributeMaxDynamicSharedMemorySize, E_SMEM);
    cudaFuncSetAttribute(o_kernel, cudaFuncAttributeMaxDynamicSharedMemorySize, O_SMEM);

    proj_kernel<<<dim3(128, 2), 256, P_SMEM>>>(k1, W1, b1, k2, W2, b2);
    vpack_kernel<<<dim3(32, B_, 2), 256>>>(v1, v2);

    score_kernel<<<dim3(16, 16, B_), 256, SC_SMEM>>>();
    maxreduce_kernel<<<dim3((B_ * N_) / 256, 2), 256>>>();

    exppack_kernel<<<dim3(16, 16, B_), 256, E_SMEM>>>();
    sumreduce_kernel<<<dim3((B_ * N_) / 256, 2), 256>>>();

    o_kernel<<<dim3(32, B_, 2), 256, O_SMEM>>>(o2_out, o1_out);
}